// round 1
// baseline (speedup 1.0000x reference)
#include <cuda_runtime.h>
#include <math.h>
#include <stdint.h>

#define NPTS 524288
#define NLEV 16
#define TSZ  524288
#define NWARPS_BLK 8
#define NTHREADS 256
#define PBATCH 2
#define NBLOCKS 1184

// ---- shared memory layout (float offsets) ----
#define OFF_WS0   0        // [32][64]  2048
#define OFF_WS0T  2048     // [64][32]  2048 (transposed ws0 for backward)
#define OFF_WS1   4096     // [64][16]  1024
#define OFF_WC0   5120     // [31][64]  1984
#define OFF_WC1   7104     // [64][64]  4096
#define OFF_WC2   11200    // [64][3]   192
#define OFF_WN0   11392    // [15][64]  960
#define OFF_WN1   12352    // [64][3]   192
#define OFF_WM0   12544    // [15][32]  480
#define OFF_WM1   13024    // [32]      32
#define OFF_BM0   13056    // [32]      32
#define OFF_BM1   13088    // [1]       1
#define OFF_RES   13089    // [16]      16 (float(res))
#define OFF_DENSE 13105    // [16]      16 (0/1)
#define OFF_SCR   13124
// per-warp scratch: enc[2*32]=64, dfe[2*96]=192, hbuf[2*64]=128, geo[2*16]=32  -> 416
#define SCR_PER_WARP 416
#define SMEM_FLOATS (OFF_SCR + NWARPS_BLK * SCR_PER_WARP)

struct HGParams { int res[16]; int dense[16]; };

__device__ __forceinline__ float warpAllSum(float v) {
    #pragma unroll
    for (int o = 16; o > 0; o >>= 1) v += __shfl_xor_sync(0xffffffffu, v, o);
    return v;
}

__device__ __forceinline__ float sigm(float v) { return 1.0f / (1.0f + expf(-v)); }

__device__ __forceinline__ float sel3(int lane, float a, float b, float c) {
    return lane == 0 ? a : (lane == 1 ? b : c);
}

extern __shared__ float smem[];

__global__ __launch_bounds__(NTHREADS, 2) void nerf_kernel(
    const float* __restrict__ x,
    const float* __restrict__ tables,
    const float* __restrict__ ws0,
    const float* __restrict__ ws1,
    const float* __restrict__ wc0,
    const float* __restrict__ wc1,
    const float* __restrict__ wc2,
    const float* __restrict__ wn0,
    const float* __restrict__ wn1,
    const float* __restrict__ wm0,
    const float* __restrict__ bm0,
    const float* __restrict__ wm1,
    const float* __restrict__ bm1,
    float* __restrict__ out,
    HGParams prm)
{
    const int tid = threadIdx.x;

    // ---- stage weights in shared ----
    for (int i = tid; i < 2048; i += NTHREADS) smem[OFF_WS0 + i] = ws0[i];
    for (int i = tid; i < 2048; i += NTHREADS) { int k = i >> 5, e = i & 31; smem[OFF_WS0T + i] = ws0[e * 64 + k]; }
    for (int i = tid; i < 1024; i += NTHREADS) smem[OFF_WS1 + i] = ws1[i];
    for (int i = tid; i < 1984; i += NTHREADS) smem[OFF_WC0 + i] = wc0[i];
    for (int i = tid; i < 4096; i += NTHREADS) smem[OFF_WC1 + i] = wc1[i];
    for (int i = tid; i < 192;  i += NTHREADS) smem[OFF_WC2 + i] = wc2[i];
    for (int i = tid; i < 960;  i += NTHREADS) smem[OFF_WN0 + i] = wn0[i];
    for (int i = tid; i < 192;  i += NTHREADS) smem[OFF_WN1 + i] = wn1[i];
    for (int i = tid; i < 480;  i += NTHREADS) smem[OFF_WM0 + i] = wm0[i];
    for (int i = tid; i < 32;   i += NTHREADS) smem[OFF_WM1 + i] = wm1[i];
    for (int i = tid; i < 32;   i += NTHREADS) smem[OFF_BM0 + i] = bm0[i];
    if (tid == 0) smem[OFF_BM1] = bm1[0];
    if (tid < 16) {
        smem[OFF_RES + tid] = (float)prm.res[tid];
        smem[OFF_DENSE + tid] = prm.dense[tid] ? 1.0f : 0.0f;
    }
    __syncthreads();

    const int lane = tid & 31;
    const int warpInBlk = tid >> 5;
    const int gwarp = blockIdx.x * NWARPS_BLK + warpInBlk;
    const int nwarp = gridDim.x * NWARPS_BLK;

    float* scr  = smem + OFF_SCR + warpInBlk * SCR_PER_WARP;
    float* enc  = scr;          // [2][32]
    float* dfe  = scr + 64;     // [2][32*3]
    float* hbuf = scr + 256;    // [2][64]
    float* geo  = scr + 384;    // [2][16]  (geo[pt*16+0] = sigma)

    for (int pbase = gwarp * PBATCH; pbase < NPTS; pbase += nwarp * PBATCH) {
        // ---- load points ----
        float xn[PBATCH][3], dirv[PBATCH][3];
        #pragma unroll
        for (int pt = 0; pt < PBATCH; ++pt) {
            const float* xp = x + (size_t)(pbase + pt) * 6;
            #pragma unroll
            for (int d = 0; d < 3; ++d) {
                float v = __ldg(xp + d);
                v = (v + 1.0f) * 0.5f;
                xn[pt][d] = fminf(fmaxf(v, 0.0f), 1.0f);
                dirv[pt][d] = __ldg(xp + 3 + d);
            }
        }

        // ---- hashgrid encode + per-level gradient terms ----
        #pragma unroll
        for (int pt = 0; pt < PBATCH; ++pt) {
            #pragma unroll
            for (int it = 0; it < 4; ++it) {
                int t = it * 32 + lane;
                int l = t >> 3;          // level
                int crn = t & 7;         // corner
                float resf = smem[OFF_RES + l];
                int res = (int)resf;
                float rm1 = resf - 1.0f;
                bool dense = smem[OFF_DENSE + l] != 0.0f;

                float posx = xn[pt][0] * rm1; float p0x = floorf(posx); float fx = posx - p0x;
                float posy = xn[pt][1] * rm1; float p0y = floorf(posy); float fy = posy - p0y;
                float posz = xn[pt][2] * rm1; float p0z = floorf(posz); float fz = posz - p0z;
                int bx = (crn >> 2) & 1, by = (crn >> 1) & 1, bz = crn & 1;
                int cx = min((int)p0x + bx, res - 1);
                int cy = min((int)p0y + by, res - 1);
                int cz = min((int)p0z + bz, res - 1);
                unsigned idx;
                if (dense) idx = (unsigned)(cx + res * (cy + res * cz));
                else idx = ((unsigned)cx ^ ((unsigned)cy * 2654435761u) ^ ((unsigned)cz * 805459861u)) & (unsigned)(TSZ - 1);

                float2 tv = __ldg(((const float2*)tables) + (size_t)l * TSZ + idx);

                float wx = bx ? fx : 1.0f - fx;
                float wy = by ? fy : 1.0f - fy;
                float wz = bz ? fz : 1.0f - fz;
                float sx = bx ? 1.0f : -1.0f;
                float sy = by ? 1.0f : -1.0f;
                float sz = bz ? 1.0f : -1.0f;
                float scale = rm1 * 0.5f;             // d pos/d xyz
                float w  = wx * wy * wz;
                float gx = sx * wy * wz * scale;
                float gy = sy * wx * wz * scale;
                float gz = sz * wx * wy * scale;

                float v[8];
                v[0] = tv.x * w;  v[1] = tv.y * w;
                v[2] = tv.x * gx; v[3] = tv.x * gy; v[4] = tv.x * gz;
                v[5] = tv.y * gx; v[6] = tv.y * gy; v[7] = tv.y * gz;
                // all-reduce within 8-lane corner group
                #pragma unroll
                for (int o = 1; o < 8; o <<= 1) {
                    #pragma unroll
                    for (int j = 0; j < 8; ++j) v[j] += __shfl_xor_sync(0xffffffffu, v[j], o);
                }
                int g = lane & 7;
                float* encp = enc + pt * 32;
                float* dfep = dfe + pt * 96;
                if (g == 0)      encp[2 * l]     = v[0];
                else if (g == 1) encp[2 * l + 1] = v[1];
                else if (g <= 4) dfep[(2 * l) * 3 + (g - 2)]     = v[g];
                else             dfep[(2 * l + 1) * 3 + (g - 5)] = v[g];
            }
        }
        __syncwarp();

        // ---- density MLP forward: h1 = relu(enc @ ws0) ----
        float pre0[PBATCH], pre1[PBATCH];
        #pragma unroll
        for (int pt = 0; pt < PBATCH; ++pt) { pre0[pt] = 0.0f; pre1[pt] = 0.0f; }
        #pragma unroll 4
        for (int i = 0; i < 32; ++i) {
            float w0 = smem[OFF_WS0 + i * 64 + lane];
            float w1 = smem[OFF_WS0 + i * 64 + lane + 32];
            #pragma unroll
            for (int pt = 0; pt < PBATCH; ++pt) {
                float e = enc[pt * 32 + i];
                pre0[pt] = fmaf(e, w0, pre0[pt]);
                pre1[pt] = fmaf(e, w1, pre1[pt]);
            }
        }
        #pragma unroll
        for (int pt = 0; pt < PBATCH; ++pt) {
            hbuf[pt * 64 + lane]      = fmaxf(pre0[pt], 0.0f);
            hbuf[pt * 64 + lane + 32] = fmaxf(pre1[pt], 0.0f);
        }
        __syncwarp();

        // ---- h2 = h1 @ ws1 (16 outputs, split-k over half-warps) ----
        int j16 = lane & 15;
        int half = lane >> 4;
        float acc2[PBATCH];
        #pragma unroll
        for (int pt = 0; pt < PBATCH; ++pt) acc2[pt] = 0.0f;
        #pragma unroll 4
        for (int kk = 0; kk < 32; ++kk) {
            int k = half * 32 + kk;
            float wv = smem[OFF_WS1 + k * 16 + j16];
            #pragma unroll
            for (int pt = 0; pt < PBATCH; ++pt)
                acc2[pt] = fmaf(hbuf[pt * 64 + k], wv, acc2[pt]);
        }
        #pragma unroll
        for (int pt = 0; pt < PBATCH; ++pt) {
            acc2[pt] += __shfl_xor_sync(0xffffffffu, acc2[pt], 16);
        }
        if (lane < 16) {
            #pragma unroll
            for (int pt = 0; pt < PBATCH; ++pt) geo[pt * 16 + lane] = acc2[pt];
        }
        __syncwarp();

        // ---- backward: genc = ws0 @ (relu' * ws1[:,0]) ----
        float w10a = smem[OFF_WS1 + lane * 16];
        float w10b = smem[OFF_WS1 + (lane + 32) * 16];
        #pragma unroll
        for (int pt = 0; pt < PBATCH; ++pt) {
            hbuf[pt * 64 + lane]      = pre0[pt] > 0.0f ? w10a : 0.0f;
            hbuf[pt * 64 + lane + 32] = pre1[pt] > 0.0f ? w10b : 0.0f;
        }
        __syncwarp();
        float genc[PBATCH];
        #pragma unroll
        for (int pt = 0; pt < PBATCH; ++pt) genc[pt] = 0.0f;
        #pragma unroll 4
        for (int k = 0; k < 64; ++k) {
            float wv = smem[OFF_WS0T + k * 32 + lane];
            #pragma unroll
            for (int pt = 0; pt < PBATCH; ++pt)
                genc[pt] = fmaf(hbuf[pt * 64 + k], wv, genc[pt]);
        }

        // ---- grad_xyz and normal ----
        float nrm[PBATCH][3];
        #pragma unroll
        for (int pt = 0; pt < PBATCH; ++pt) {
            #pragma unroll
            for (int d = 0; d < 3; ++d)
                nrm[pt][d] = warpAllSum(genc[pt] * dfe[pt * 96 + lane * 3 + d]);
        }
        float nOut[PBATCH][3];
        #pragma unroll
        for (int pt = 0; pt < PBATCH; ++pt) {
            float n0 = -nrm[pt][0], n1 = -nrm[pt][1], n2 = -nrm[pt][2];
            float nn = sqrtf(n0 * n0 + n1 * n1 + n2 * n2);
            float inv = 1.0f / fmaxf(nn, 1e-8f);
            nOut[pt][0] = n0 * inv; nOut[pt][1] = n1 * inv; nOut[pt][2] = n2 * inv;
        }

        // ---- pred_normal: l2norm(relu(geo @ wn0) @ wn1) ----
        float t0[PBATCH], t1[PBATCH];
        #pragma unroll
        for (int pt = 0; pt < PBATCH; ++pt) { t0[pt] = 0.0f; t1[pt] = 0.0f; }
        #pragma unroll
        for (int i = 0; i < 15; ++i) {
            float w0 = smem[OFF_WN0 + i * 64 + lane];
            float w1 = smem[OFF_WN0 + i * 64 + lane + 32];
            #pragma unroll
            for (int pt = 0; pt < PBATCH; ++pt) {
                float g = geo[pt * 16 + 1 + i];
                t0[pt] = fmaf(g, w0, t0[pt]);
                t1[pt] = fmaf(g, w1, t1[pt]);
            }
        }
        #pragma unroll
        for (int pt = 0; pt < PBATCH; ++pt) { t0[pt] = fmaxf(t0[pt], 0.0f); t1[pt] = fmaxf(t1[pt], 0.0f); }
        float pnOut[PBATCH][3];
        #pragma unroll
        for (int d = 0; d < 3; ++d) {
            float wA = smem[OFF_WN1 + lane * 3 + d];
            float wB = smem[OFF_WN1 + (lane + 32) * 3 + d];
            #pragma unroll
            for (int pt = 0; pt < PBATCH; ++pt)
                pnOut[pt][d] = warpAllSum(t0[pt] * wA + t1[pt] * wB);
        }
        #pragma unroll
        for (int pt = 0; pt < PBATCH; ++pt) {
            float n0 = pnOut[pt][0], n1 = pnOut[pt][1], n2 = pnOut[pt][2];
            float nn = sqrtf(n0 * n0 + n1 * n1 + n2 * n2);
            float inv = 1.0f / fmaxf(nn, 1e-8f);
            pnOut[pt][0] = n0 * inv; pnOut[pt][1] = n1 * inv; pnOut[pt][2] = n2 * inv;
        }

        // ---- color MLP: hcol = [sh16(d), geo15] ----
        float c0a[PBATCH], c0b[PBATCH];
        #pragma unroll
        for (int pt = 0; pt < PBATCH; ++pt) {
            float dx = dirv[pt][0], dy = dirv[pt][1], dz = dirv[pt][2];
            float xy = dx * dy, xz = dx * dz, yz = dy * dz;
            float x2 = dx * dx, y2 = dy * dy, z2 = dz * dz;
            float sh[16];
            sh[0] = 0.28209479177387814f;
            sh[1] = -0.48860251190291987f * dy;
            sh[2] =  0.48860251190291987f * dz;
            sh[3] = -0.48860251190291987f * dx;
            sh[4] =  1.0925484305920792f * xy;
            sh[5] = -1.0925484305920792f * yz;
            sh[6] =  0.94617469575756f * z2 - 0.31539156525252005f;
            sh[7] = -1.0925484305920792f * xz;
            sh[8] =  0.5462742152960396f * (x2 - y2);
            sh[9] =  0.5900435899266435f * dy * (-3.0f * x2 + y2);
            sh[10] = 2.890611442640554f * xy * dz;
            sh[11] = 0.4570457994644657f * dy * (1.0f - 5.0f * z2);
            sh[12] = 0.3731763325901154f * dz * (5.0f * z2 - 3.0f);
            sh[13] = 0.4570457994644657f * dx * (1.0f - 5.0f * z2);
            sh[14] = 1.445305721320277f * dz * (x2 - y2);
            sh[15] = 0.5900435899266435f * dx * (x2 - 3.0f * y2);
            float a = 0.0f, b = 0.0f;
            #pragma unroll
            for (int i = 0; i < 16; ++i) {
                a = fmaf(sh[i], smem[OFF_WC0 + i * 64 + lane], a);
                b = fmaf(sh[i], smem[OFF_WC0 + i * 64 + lane + 32], b);
            }
            #pragma unroll
            for (int i = 0; i < 15; ++i) {
                float g = geo[pt * 16 + 1 + i];
                a = fmaf(g, smem[OFF_WC0 + (16 + i) * 64 + lane], a);
                b = fmaf(g, smem[OFF_WC0 + (16 + i) * 64 + lane + 32], b);
            }
            c0a[pt] = fmaxf(a, 0.0f);
            c0b[pt] = fmaxf(b, 0.0f);
        }
        __syncwarp();
        #pragma unroll
        for (int pt = 0; pt < PBATCH; ++pt) {
            hbuf[pt * 64 + lane]      = c0a[pt];
            hbuf[pt * 64 + lane + 32] = c0b[pt];
        }
        __syncwarp();
        float c1a[PBATCH], c1b[PBATCH];
        #pragma unroll
        for (int pt = 0; pt < PBATCH; ++pt) { c1a[pt] = 0.0f; c1b[pt] = 0.0f; }
        #pragma unroll 4
        for (int k = 0; k < 64; ++k) {
            float w0 = smem[OFF_WC1 + k * 64 + lane];
            float w1 = smem[OFF_WC1 + k * 64 + lane + 32];
            #pragma unroll
            for (int pt = 0; pt < PBATCH; ++pt) {
                float v = hbuf[pt * 64 + k];
                c1a[pt] = fmaf(v, w0, c1a[pt]);
                c1b[pt] = fmaf(v, w1, c1b[pt]);
            }
        }
        #pragma unroll
        for (int pt = 0; pt < PBATCH; ++pt) { c1a[pt] = fmaxf(c1a[pt], 0.0f); c1b[pt] = fmaxf(c1b[pt], 0.0f); }
        float rgbOut[PBATCH][3];
        #pragma unroll
        for (int d = 0; d < 3; ++d) {
            float wA = smem[OFF_WC2 + lane * 3 + d];
            float wB = smem[OFF_WC2 + (lane + 32) * 3 + d];
            #pragma unroll
            for (int pt = 0; pt < PBATCH; ++pt)
                rgbOut[pt][d] = warpAllSum(c1a[pt] * wA + c1b[pt] * wB);
        }
        #pragma unroll
        for (int pt = 0; pt < PBATCH; ++pt) {
            #pragma unroll
            for (int d = 0; d < 3; ++d) rgbOut[pt][d] = sigm(rgbOut[pt][d]);
        }

        // ---- mirror head ----
        float mir[PBATCH];
        {
            float mm[PBATCH];
            #pragma unroll
            for (int pt = 0; pt < PBATCH; ++pt) mm[pt] = smem[OFF_BM0 + lane];
            #pragma unroll
            for (int i = 0; i < 15; ++i) {
                float w = smem[OFF_WM0 + i * 32 + lane];
                #pragma unroll
                for (int pt = 0; pt < PBATCH; ++pt)
                    mm[pt] = fmaf(geo[pt * 16 + 1 + i], w, mm[pt]);
            }
            float wm1v = smem[OFF_WM1 + lane];
            float bm1v = smem[OFF_BM1];
            #pragma unroll
            for (int pt = 0; pt < PBATCH; ++pt) {
                float m = mm[pt];
                m = m > 0.0f ? m : 0.01f * m;   // leaky_relu 0.01
                float s = warpAllSum(m * wm1v);
                mir[pt] = sigm(s + bm1v);
            }
        }

        // ---- outputs ----
        #pragma unroll
        for (int pt = 0; pt < PBATCH; ++pt) {
            size_t p = (size_t)(pbase + pt);
            if (lane == 0) out[p] = geo[pt * 16];
            if (lane < 15) out[(size_t)NPTS + p * 15 + lane] = geo[pt * 16 + 1 + lane];
            if (lane < 3) {
                out[(size_t)NPTS * 16 + p * 3 + lane] = sel3(lane, nOut[pt][0], nOut[pt][1], nOut[pt][2]);
                out[(size_t)NPTS * 19 + p * 3 + lane] = sel3(lane, pnOut[pt][0], pnOut[pt][1], pnOut[pt][2]);
                out[(size_t)NPTS * 22 + p * 3 + lane] = sel3(lane, rgbOut[pt][0], rgbOut[pt][1], rgbOut[pt][2]);
            }
            if (lane == 0) out[(size_t)NPTS * 25 + p] = mir[pt];
        }
    }
}

extern "C" void kernel_launch(void* const* d_in, const int* in_sizes, int n_in,
                              void* d_out, int out_size) {
    (void)in_sizes; (void)n_in; (void)out_size;
    HGParams prm;
    // replicate numpy: PLS = exp2(log2(2048*BOUND/N_LEVELS)/(N_LEVELS-1)); RES = floor(16*PLS**l)
    double pls = exp2(log2(2048.0 * 1.0 / 16.0) / 15.0);
    for (int l = 0; l < 16; ++l) {
        int r = (int)floor(16.0 * pow(pls, (double)l));
        prm.res[l] = r;
        long long r3 = (long long)r * r * r;
        prm.dense[l] = (r3 <= (long long)TSZ) ? 1 : 0;
    }
    size_t smemBytes = (size_t)SMEM_FLOATS * sizeof(float);
    cudaFuncSetAttribute(nerf_kernel, cudaFuncAttributeMaxDynamicSharedMemorySize, (int)smemBytes);
    nerf_kernel<<<NBLOCKS, NTHREADS, smemBytes>>>(
        (const float*)d_in[0],  // x
        (const float*)d_in[1],  // tables
        (const float*)d_in[2],  // ws0
        (const float*)d_in[3],  // ws1
        (const float*)d_in[4],  // wc0
        (const float*)d_in[5],  // wc1
        (const float*)d_in[6],  // wc2
        (const float*)d_in[7],  // wn0
        (const float*)d_in[8],  // wn1
        (const float*)d_in[9],  // wm0
        (const float*)d_in[10], // bm0
        (const float*)d_in[11], // wm1
        (const float*)d_in[12], // bm1
        (float*)d_out, prm);
}

// round 2
// speedup vs baseline: 1.2271x; 1.2271x over previous
#include <cuda_runtime.h>
#include <math.h>
#include <stdint.h>

#define NPTS 524288
#define TSZ  524288
#define NTHREADS 256
#define NWARPS_BLK 8
#define NBLOCKS 296
#define FULL 0xffffffffu

typedef unsigned long long u64;

// ---- shared memory layout (float offsets) ----
#define OFF_WS0   0        // [32][64]  2048
#define OFF_WS0T  2048     // [64][32]  2048
#define OFF_WS1   4096     // [64][16]  1024
#define OFF_WC0   5120     // [31][64]  1984
#define OFF_WC1   7104     // [64][64]  4096
#define OFF_WC2   11200    // [64][3]   192
#define OFF_WN0   11392    // [15][64]  960
#define OFF_WN1   12352    // [64][3]   192
#define OFF_WM0   12544    // [15][32]  480
#define OFF_WM1   13024    // [32]
#define OFF_BM0   13056    // [32]
#define OFF_BM1   13088    // [1]
#define SMEM_FLOATS 13089

struct HGParams { int res[16]; int dense[16]; };

// ---- packed f32x2 helpers ----
__device__ __forceinline__ u64 pk(float lo, float hi) {
    u64 r; asm("mov.b64 %0,{%1,%2};" : "=l"(r) : "f"(lo), "f"(hi)); return r;
}
__device__ __forceinline__ void upk(u64 v, float& lo, float& hi) {
    asm("mov.b64 {%0,%1},%2;" : "=f"(lo), "=f"(hi) : "l"(v));
}
__device__ __forceinline__ u64 bc2(float w) { return pk(w, w); }
__device__ __forceinline__ u64 fma2(u64 a, u64 b, u64 c) {
    u64 d; asm("fma.rn.f32x2 %0,%1,%2,%3;" : "=l"(d) : "l"(a), "l"(b), "l"(c)); return d;
}
__device__ __forceinline__ u64 mul2(u64 a, u64 b) {
    u64 d; asm("mul.rn.f32x2 %0,%1,%2;" : "=l"(d) : "l"(a), "l"(b)); return d;
}
__device__ __forceinline__ u64 add2(u64 a, u64 b) {
    u64 d; asm("add.rn.f32x2 %0,%1,%2;" : "=l"(d) : "l"(a), "l"(b)); return d;
}
__device__ __forceinline__ u64 relu2(u64 v) {
    float a, b; upk(v, a, b); return pk(fmaxf(a, 0.f), fmaxf(b, 0.f));
}
__device__ __forceinline__ u64 allsum2(u64 v) {
    #pragma unroll
    for (int o = 16; o > 0; o >>= 1) v = add2(v, __shfl_xor_sync(FULL, v, o));
    return v;
}
__device__ __forceinline__ float sigm(float v) { return 1.0f / (1.0f + expf(-v)); }
__device__ __forceinline__ float sel3(int lane, float a, float b, float c) {
    return lane == 0 ? a : (lane == 1 ? b : c);
}

extern __shared__ float smem[];

__global__ __launch_bounds__(NTHREADS, 2) void nerf_kernel(
    const float* __restrict__ x,
    const float* __restrict__ tables,
    const float* __restrict__ ws0, const float* __restrict__ ws1,
    const float* __restrict__ wc0, const float* __restrict__ wc1, const float* __restrict__ wc2,
    const float* __restrict__ wn0, const float* __restrict__ wn1,
    const float* __restrict__ wm0, const float* __restrict__ bm0,
    const float* __restrict__ wm1, const float* __restrict__ bm1,
    float* __restrict__ out, HGParams prm)
{
    const int tid = threadIdx.x;
    // ---- stage weights ----
    for (int i = tid; i < 2048; i += NTHREADS) smem[OFF_WS0 + i] = ws0[i];
    for (int i = tid; i < 2048; i += NTHREADS) { int k = i >> 5, e = i & 31; smem[OFF_WS0T + i] = ws0[e * 64 + k]; }
    for (int i = tid; i < 1024; i += NTHREADS) smem[OFF_WS1 + i] = ws1[i];
    for (int i = tid; i < 1984; i += NTHREADS) smem[OFF_WC0 + i] = wc0[i];
    for (int i = tid; i < 4096; i += NTHREADS) smem[OFF_WC1 + i] = wc1[i];
    for (int i = tid; i < 192;  i += NTHREADS) smem[OFF_WC2 + i] = wc2[i];
    for (int i = tid; i < 960;  i += NTHREADS) smem[OFF_WN0 + i] = wn0[i];
    for (int i = tid; i < 192;  i += NTHREADS) smem[OFF_WN1 + i] = wn1[i];
    for (int i = tid; i < 480;  i += NTHREADS) smem[OFF_WM0 + i] = wm0[i];
    for (int i = tid; i < 32;   i += NTHREADS) smem[OFF_WM1 + i] = wm1[i];
    for (int i = tid; i < 32;   i += NTHREADS) smem[OFF_BM0 + i] = bm0[i];
    if (tid == 0) smem[OFF_BM1] = bm1[0];
    __syncthreads();

    const int lane = tid & 31;
    const int gwarp = blockIdx.x * NWARPS_BLK + (tid >> 5);
    const int nwarp = gridDim.x * NWARPS_BLK;
    const int j16 = lane & 15;

    // per-lane hash level setup: lane -> (level = lane>>1, feature = lane&1)
    const int lvl = lane >> 1;
    const int feat1 = lane & 1;
    const int res = prm.res[lvl];
    const int dense = prm.dense[lvl];
    const int resm1 = res - 1;
    const float rm1 = (float)resm1;
    const float gscale = rm1 * 0.5f;
    const unsigned my = dense ? (unsigned)res : 2654435761u;
    const unsigned mz = dense ? (unsigned)(res * res) : 805459861u;
    const float2* __restrict__ tabl = ((const float2*)tables) + (size_t)lvl * TSZ;

    const float* sws0  = smem + OFF_WS0;
    const float* sws0t = smem + OFF_WS0T;
    const float* sws1  = smem + OFF_WS1;
    const float* swc0  = smem + OFF_WC0;
    const float* swc1  = smem + OFF_WC1;
    const float* swc2  = smem + OFF_WC2;
    const float* swn0  = smem + OFF_WN0;
    const float* swn1  = smem + OFF_WN1;
    const float* swm0  = smem + OFF_WM0;
    const float* swm1  = smem + OFF_WM1;
    const float* sbm0  = smem + OFF_BM0;

    for (int pbase = gwarp * 4; pbase < NPTS; pbase += nwarp * 4) {
        // ---- load 4 points ----
        float xn[4][3], dirv[4][3];
        #pragma unroll
        for (int pt = 0; pt < 4; ++pt) {
            const float* xp = x + (size_t)(pbase + pt) * 6;
            #pragma unroll
            for (int d = 0; d < 3; ++d) {
                float v = __ldg(xp + d);
                xn[pt][d] = fminf(fmaxf((v + 1.0f) * 0.5f, 0.0f), 1.0f);
                dirv[pt][d] = __ldg(xp + 3 + d);
            }
        }

        // ---- hashgrid: lane owns (level,feature); 8 serial corner gathers ----
        float enc_s[4], gx_s[4], gy_s[4], gz_s[4];
        #pragma unroll
        for (int pt = 0; pt < 4; ++pt) {
            float px = xn[pt][0] * rm1, py = xn[pt][1] * rm1, pz = xn[pt][2] * rm1;
            float fpx = floorf(px), fpy = floorf(py), fpz = floorf(pz);
            float fx = px - fpx, fy = py - fpy, fz = pz - fpz;
            int ix = (int)fpx, iy = (int)fpy, iz = (int)fpz;
            int ix1 = min(ix + 1, resm1), iy1 = min(iy + 1, resm1), iz1 = min(iz + 1, resm1);
            unsigned ax[2], ay[2], az[2];
            ax[0] = (unsigned)ix;  ax[1] = (unsigned)ix1;
            ay[0] = (unsigned)iy * my;  ay[1] = (unsigned)iy1 * my;
            az[0] = (unsigned)iz * mz;  az[1] = (unsigned)iz1 * mz;
            float2 tv[8];
            #pragma unroll
            for (int c = 0; c < 8; ++c) {
                int bx = (c >> 2) & 1, by = (c >> 1) & 1, bz = c & 1;
                unsigned idx = dense ? (ax[bx] + ay[by] + az[bz])
                                     : ((ax[bx] ^ ay[by] ^ az[bz]) & (unsigned)(TSZ - 1));
                tv[c] = __ldg(tabl + idx);
            }
            float ox = 1.f - fx, oy = 1.f - fy, oz = 1.f - fz;
            float e = 0.f, gx = 0.f, gy = 0.f, gz = 0.f;
            #pragma unroll
            for (int c = 0; c < 8; ++c) {
                int bx = (c >> 2) & 1, by = (c >> 1) & 1, bz = c & 1;
                float wx = bx ? fx : ox, wy = by ? fy : oy, wz = bz ? fz : oz;
                float v = feat1 ? tv[c].y : tv[c].x;
                float wxy = wx * wy;
                e = fmaf(v, wxy * wz, e);
                float vx = bx ? v : -v, vy = by ? v : -v, vz = bz ? v : -v;
                gx = fmaf(vx, wy * wz, gx);
                gy = fmaf(vy, wx * wz, gy);
                gz = fmaf(vz, wxy, gz);
            }
            enc_s[pt] = e; gx_s[pt] = gx * gscale; gy_s[pt] = gy * gscale; gz_s[pt] = gz * gscale;
        }
        // pack pairs: P=0 -> (pt0,pt1), P=1 -> (pt2,pt3). lane index = feature index.
        u64 encP[2] = { pk(enc_s[0], enc_s[1]), pk(enc_s[2], enc_s[3]) };
        u64 dfx[2]  = { pk(gx_s[0], gx_s[1]),  pk(gx_s[2], gx_s[3]) };
        u64 dfy[2]  = { pk(gy_s[0], gy_s[1]),  pk(gy_s[2], gy_s[3]) };
        u64 dfz[2]  = { pk(gz_s[0], gz_s[1]),  pk(gz_s[2], gz_s[3]) };

        // ---- density layer0: pre[64] = enc @ ws0; lane owns outs (lane, lane+32) ----
        u64 h1[2][2] = {{0ull,0ull},{0ull,0ull}};
        #pragma unroll 4
        for (int i = 0; i < 32; ++i) {
            u64 e0 = __shfl_sync(FULL, encP[0], i);
            u64 e1 = __shfl_sync(FULL, encP[1], i);
            u64 w0 = bc2(sws0[i * 64 + lane]);
            u64 w1 = bc2(sws0[i * 64 + lane + 32]);
            h1[0][0] = fma2(e0, w0, h1[0][0]); h1[0][1] = fma2(e0, w1, h1[0][1]);
            h1[1][0] = fma2(e1, w0, h1[1][0]); h1[1][1] = fma2(e1, w1, h1[1][1]);
        }
        // relu-mask weights for backward (dh = pre>0 ? ws1[:,0] : 0), then relu
        float w10a = sws1[lane * 16], w10b = sws1[(lane + 32) * 16];
        u64 dh[2][2];
        #pragma unroll
        for (int P = 0; P < 2; ++P) {
            float a, b;
            upk(h1[P][0], a, b); dh[P][0] = pk(a > 0.f ? w10a : 0.f, b > 0.f ? w10a : 0.f);
            h1[P][0] = pk(fmaxf(a, 0.f), fmaxf(b, 0.f));
            upk(h1[P][1], a, b); dh[P][1] = pk(a > 0.f ? w10b : 0.f, b > 0.f ? w10b : 0.f);
            h1[P][1] = pk(fmaxf(a, 0.f), fmaxf(b, 0.f));
        }

        // ---- density layer1: geo[16] = h1 @ ws1 (every lane computes j16 = lane&15) ----
        u64 geo[2] = {0ull, 0ull};
        #pragma unroll 4
        for (int kk = 0; kk < 32; ++kk) {
            u64 wA = bc2(sws1[kk * 16 + j16]);
            u64 wB = bc2(sws1[(kk + 32) * 16 + j16]);
            u64 a0 = __shfl_sync(FULL, h1[0][0], kk), b0 = __shfl_sync(FULL, h1[0][1], kk);
            u64 a1 = __shfl_sync(FULL, h1[1][0], kk), b1 = __shfl_sync(FULL, h1[1][1], kk);
            geo[0] = fma2(a0, wA, fma2(b0, wB, geo[0]));
            geo[1] = fma2(a1, wA, fma2(b1, wB, geo[1]));
        }

        // ---- backward: genc[e=lane] = sum_k ws0[e][k] * dh[k] ----
        u64 genc[2] = {0ull, 0ull};
        #pragma unroll 4
        for (int kk = 0; kk < 32; ++kk) {
            u64 wA = bc2(sws0t[kk * 32 + lane]);
            u64 wB = bc2(sws0t[(kk + 32) * 32 + lane]);
            u64 dA0 = __shfl_sync(FULL, dh[0][0], kk), dB0 = __shfl_sync(FULL, dh[0][1], kk);
            u64 dA1 = __shfl_sync(FULL, dh[1][0], kk), dB1 = __shfl_sync(FULL, dh[1][1], kk);
            genc[0] = fma2(dA0, wA, fma2(dB0, wB, genc[0]));
            genc[1] = fma2(dA1, wA, fma2(dB1, wB, genc[1]));
        }

        // ---- normal = l2norm(-grad) ----
        #pragma unroll
        for (int P = 0; P < 2; ++P) {
            u64 sx = allsum2(mul2(genc[P], dfx[P]));
            u64 sy = allsum2(mul2(genc[P], dfy[P]));
            u64 sz = allsum2(mul2(genc[P], dfz[P]));
            float nx0, nx1, ny0, ny1, nz0, nz1;
            upk(sx, nx0, nx1); upk(sy, ny0, ny1); upk(sz, nz0, nz1);
            #pragma unroll
            for (int q = 0; q < 2; ++q) {
                float n0 = -(q ? nx1 : nx0), n1 = -(q ? ny1 : ny0), n2 = -(q ? nz1 : nz0);
                float inv = 1.0f / fmaxf(sqrtf(n0*n0 + n1*n1 + n2*n2), 1e-8f);
                if (lane < 3)
                    out[(size_t)NPTS * 16 + (size_t)(pbase + P * 2 + q) * 3 + lane] =
                        sel3(lane, n0 * inv, n1 * inv, n2 * inv);
            }
        }

        // ---- pred_normal ----
        {
            u64 t[2][2] = {{0ull,0ull},{0ull,0ull}};
            #pragma unroll
            for (int i = 0; i < 15; ++i) {
                u64 g0 = __shfl_sync(FULL, geo[0], i + 1);
                u64 g1 = __shfl_sync(FULL, geo[1], i + 1);
                u64 w0 = bc2(swn0[i * 64 + lane]);
                u64 w1 = bc2(swn0[i * 64 + lane + 32]);
                t[0][0] = fma2(g0, w0, t[0][0]); t[0][1] = fma2(g0, w1, t[0][1]);
                t[1][0] = fma2(g1, w0, t[1][0]); t[1][1] = fma2(g1, w1, t[1][1]);
            }
            t[0][0] = relu2(t[0][0]); t[0][1] = relu2(t[0][1]);
            t[1][0] = relu2(t[1][0]); t[1][1] = relu2(t[1][1]);
            float pn[2][3][2];
            #pragma unroll
            for (int d = 0; d < 3; ++d) {
                u64 wA = bc2(swn1[lane * 3 + d]);
                u64 wB = bc2(swn1[(lane + 32) * 3 + d]);
                #pragma unroll
                for (int P = 0; P < 2; ++P) {
                    u64 s = allsum2(fma2(t[P][0], wA, mul2(t[P][1], wB)));
                    upk(s, pn[P][d][0], pn[P][d][1]);
                }
            }
            #pragma unroll
            for (int P = 0; P < 2; ++P)
                #pragma unroll
                for (int q = 0; q < 2; ++q) {
                    float n0 = pn[P][0][q], n1 = pn[P][1][q], n2 = pn[P][2][q];
                    float inv = 1.0f / fmaxf(sqrtf(n0*n0 + n1*n1 + n2*n2), 1e-8f);
                    if (lane < 3)
                        out[(size_t)NPTS * 19 + (size_t)(pbase + P * 2 + q) * 3 + lane] =
                            sel3(lane, n0 * inv, n1 * inv, n2 * inv);
                }
        }

        // ---- color ----
        {
            u64 hc[2][2];
            #pragma unroll
            for (int P = 0; P < 2; ++P) {
                u64 X = pk(dirv[2*P][0], dirv[2*P+1][0]);
                u64 Y = pk(dirv[2*P][1], dirv[2*P+1][1]);
                u64 Z = pk(dirv[2*P][2], dirv[2*P+1][2]);
                u64 XY = mul2(X, Y), XZ = mul2(X, Z), YZ = mul2(Y, Z);
                u64 X2 = mul2(X, X), Y2 = mul2(Y, Y), Z2 = mul2(Z, Z);
                u64 shp[16];
                shp[0] = bc2(0.28209479177387814f);
                shp[1] = mul2(bc2(-0.48860251190291987f), Y);
                shp[2] = mul2(bc2(0.48860251190291987f), Z);
                shp[3] = mul2(bc2(-0.48860251190291987f), X);
                shp[4] = mul2(bc2(1.0925484305920792f), XY);
                shp[5] = mul2(bc2(-1.0925484305920792f), YZ);
                shp[6] = fma2(bc2(0.94617469575756f), Z2, bc2(-0.31539156525252005f));
                shp[7] = mul2(bc2(-1.0925484305920792f), XZ);
                shp[8] = mul2(bc2(0.5462742152960396f), fma2(Y2, bc2(-1.f), X2));
                shp[9] = mul2(bc2(0.5900435899266435f), mul2(Y, fma2(bc2(-3.f), X2, Y2)));
                shp[10] = mul2(bc2(2.890611442640554f), mul2(XY, Z));
                shp[11] = mul2(bc2(0.4570457994644657f), mul2(Y, fma2(bc2(-5.f), Z2, bc2(1.f))));
                shp[12] = mul2(bc2(0.3731763325901154f), mul2(Z, fma2(bc2(5.f), Z2, bc2(-3.f))));
                shp[13] = mul2(bc2(0.4570457994644657f), mul2(X, fma2(bc2(-5.f), Z2, bc2(1.f))));
                shp[14] = mul2(bc2(1.445305721320277f), mul2(Z, fma2(Y2, bc2(-1.f), X2)));
                shp[15] = mul2(bc2(0.5900435899266435f), mul2(X, fma2(bc2(-3.f), Y2, X2)));
                u64 a = 0ull, b = 0ull;
                #pragma unroll
                for (int i = 0; i < 16; ++i) {
                    a = fma2(shp[i], bc2(swc0[i * 64 + lane]), a);
                    b = fma2(shp[i], bc2(swc0[i * 64 + lane + 32]), b);
                }
                #pragma unroll
                for (int i = 0; i < 15; ++i) {
                    u64 g = __shfl_sync(FULL, geo[P], i + 1);
                    a = fma2(g, bc2(swc0[(16 + i) * 64 + lane]), a);
                    b = fma2(g, bc2(swc0[(16 + i) * 64 + lane + 32]), b);
                }
                hc[P][0] = relu2(a); hc[P][1] = relu2(b);
            }
            u64 c1[2][2] = {{0ull,0ull},{0ull,0ull}};
            #pragma unroll 4
            for (int kk = 0; kk < 32; ++kk) {
                u64 w00 = bc2(swc1[kk * 64 + lane]);
                u64 w01 = bc2(swc1[kk * 64 + lane + 32]);
                u64 w10 = bc2(swc1[(kk + 32) * 64 + lane]);
                u64 w11 = bc2(swc1[(kk + 32) * 64 + lane + 32]);
                u64 hA0 = __shfl_sync(FULL, hc[0][0], kk), hB0 = __shfl_sync(FULL, hc[0][1], kk);
                u64 hA1 = __shfl_sync(FULL, hc[1][0], kk), hB1 = __shfl_sync(FULL, hc[1][1], kk);
                c1[0][0] = fma2(hA0, w00, fma2(hB0, w10, c1[0][0]));
                c1[0][1] = fma2(hA0, w01, fma2(hB0, w11, c1[0][1]));
                c1[1][0] = fma2(hA1, w00, fma2(hB1, w10, c1[1][0]));
                c1[1][1] = fma2(hA1, w01, fma2(hB1, w11, c1[1][1]));
            }
            #pragma unroll
            for (int P = 0; P < 2; ++P) { c1[P][0] = relu2(c1[P][0]); c1[P][1] = relu2(c1[P][1]); }
            #pragma unroll
            for (int d = 0; d < 3; ++d) {
                u64 wA = bc2(swc2[lane * 3 + d]);
                u64 wB = bc2(swc2[(lane + 32) * 3 + d]);
                #pragma unroll
                for (int P = 0; P < 2; ++P) {
                    u64 s = allsum2(fma2(c1[P][0], wA, mul2(c1[P][1], wB)));
                    float r0, r1; upk(s, r0, r1);
                    if (lane < 3) {
                        float vv = sel3(lane, d == 0 ? 1.f : 0.f, d == 1 ? 1.f : 0.f, d == 2 ? 1.f : 0.f);
                        (void)vv;
                    }
                    if (lane == d) {
                        out[(size_t)NPTS * 22 + (size_t)(pbase + P * 2 + 0) * 3 + d] = sigm(r0);
                        out[(size_t)NPTS * 22 + (size_t)(pbase + P * 2 + 1) * 3 + d] = sigm(r1);
                    }
                }
            }
        }

        // ---- mirror head ----
        {
            u64 m[2]; m[0] = m[1] = bc2(sbm0[lane]);
            #pragma unroll
            for (int i = 0; i < 15; ++i) {
                u64 w = bc2(swm0[i * 32 + lane]);
                u64 g0 = __shfl_sync(FULL, geo[0], i + 1);
                u64 g1 = __shfl_sync(FULL, geo[1], i + 1);
                m[0] = fma2(g0, w, m[0]); m[1] = fma2(g1, w, m[1]);
            }
            float bm1v = smem[OFF_BM1];
            u64 wv = bc2(swm1[lane]);
            #pragma unroll
            for (int P = 0; P < 2; ++P) {
                float a, b; upk(m[P], a, b);
                a = a > 0.f ? a : 0.01f * a;
                b = b > 0.f ? b : 0.01f * b;
                u64 s = allsum2(mul2(pk(a, b), wv));
                float s0, s1; upk(s, s0, s1);
                if (lane == 0) {
                    out[(size_t)NPTS * 25 + (pbase + P * 2 + 0)] = sigm(s0 + bm1v);
                    out[(size_t)NPTS * 25 + (pbase + P * 2 + 1)] = sigm(s1 + bm1v);
                }
            }
        }

        // ---- sigma + geo_feat outputs (lane j<16 holds geo[j] for both pts of each pair) ----
        #pragma unroll
        for (int P = 0; P < 2; ++P) {
            float gA, gB; upk(geo[P], gA, gB);
            size_t p0 = (size_t)(pbase + P * 2), p1 = p0 + 1;
            if (lane == 0) { out[p0] = gA; out[p1] = gB; }
            if (lane >= 1 && lane < 16) {
                out[(size_t)NPTS + p0 * 15 + (lane - 1)] = gA;
                out[(size_t)NPTS + p1 * 15 + (lane - 1)] = gB;
            }
        }
    }
}

extern "C" void kernel_launch(void* const* d_in, const int* in_sizes, int n_in,
                              void* d_out, int out_size) {
    (void)in_sizes; (void)n_in; (void)out_size;
    HGParams prm;
    double pls = exp2(log2(2048.0 * 1.0 / 16.0) / 15.0);
    for (int l = 0; l < 16; ++l) {
        int r = (int)floor(16.0 * pow(pls, (double)l));
        prm.res[l] = r;
        long long r3 = (long long)r * r * r;
        prm.dense[l] = (r3 <= (long long)TSZ) ? 1 : 0;
    }
    size_t smemBytes = (size_t)SMEM_FLOATS * sizeof(float);
    cudaFuncSetAttribute(nerf_kernel, cudaFuncAttributeMaxDynamicSharedMemorySize, (int)smemBytes);
    nerf_kernel<<<NBLOCKS, NTHREADS, smemBytes>>>(
        (const float*)d_in[0], (const float*)d_in[1],
        (const float*)d_in[2], (const float*)d_in[3],
        (const float*)d_in[4], (const float*)d_in[5], (const float*)d_in[6],
        (const float*)d_in[7], (const float*)d_in[8],
        (const float*)d_in[9], (const float*)d_in[10],
        (const float*)d_in[11], (const float*)d_in[12],
        (float*)d_out, prm);
}

// round 3
// speedup vs baseline: 1.3747x; 1.1203x over previous
#include <cuda_runtime.h>
#include <math.h>
#include <stdint.h>

#define NPTS 524288
#define TSZ  524288
#define NTHREADS 256
#define NWARPS_BLK 8
#define NBLOCKS 296
#define FULL 0xffffffffu
#define NPAIR 4   // 8 points per warp iteration

typedef unsigned long long u64;

// ---- shared memory layout (float offsets) ----
#define OFF_WS0   0        // [32][64]
#define OFF_WS0T  2048     // [64][32]
#define OFF_WS1   4096     // [64][16]
#define OFF_WC0   5120     // [31][64]
#define OFF_WC1   7104     // [64][64]
#define OFF_WC2   11200    // [64][3]
#define OFF_WN0   11392    // [15][64]
#define OFF_WN1   12352    // [64][3]
#define OFF_WM0   12544    // [15][32]
#define OFF_WM1   13024    // [32]
#define OFF_BM0   13056    // [32]
#define OFF_BM1   13088    // [1]
#define SMEM_FLOATS 13089

struct HGParams { int res[16]; int dense[16]; };

__device__ __forceinline__ u64 pk(float lo, float hi) {
    u64 r; asm("mov.b64 %0,{%1,%2};" : "=l"(r) : "f"(lo), "f"(hi)); return r;
}
__device__ __forceinline__ void upk(u64 v, float& lo, float& hi) {
    asm("mov.b64 {%0,%1},%2;" : "=f"(lo), "=f"(hi) : "l"(v));
}
__device__ __forceinline__ u64 bc2(float w) { return pk(w, w); }
__device__ __forceinline__ u64 fma2(u64 a, u64 b, u64 c) {
    u64 d; asm("fma.rn.f32x2 %0,%1,%2,%3;" : "=l"(d) : "l"(a), "l"(b), "l"(c)); return d;
}
__device__ __forceinline__ u64 mul2(u64 a, u64 b) {
    u64 d; asm("mul.rn.f32x2 %0,%1,%2;" : "=l"(d) : "l"(a), "l"(b)); return d;
}
__device__ __forceinline__ u64 add2(u64 a, u64 b) {
    u64 d; asm("add.rn.f32x2 %0,%1,%2;" : "=l"(d) : "l"(a), "l"(b)); return d;
}
__device__ __forceinline__ u64 relu2(u64 v) {
    float a, b; upk(v, a, b); return pk(fmaxf(a, 0.f), fmaxf(b, 0.f));
}
__device__ __forceinline__ u64 allsum2(u64 v) {
    #pragma unroll
    for (int o = 16; o > 0; o >>= 1) v = add2(v, __shfl_xor_sync(FULL, v, o));
    return v;
}
__device__ __forceinline__ float sigm(float v) { return 1.0f / (1.0f + expf(-v)); }
__device__ __forceinline__ float sel3(int lane, float a, float b, float c) {
    return lane == 0 ? a : (lane == 1 ? b : c);
}

extern __shared__ float smem[];

__global__ __launch_bounds__(NTHREADS, 2) void nerf_kernel(
    const float* __restrict__ x,
    const float* __restrict__ tables,
    const float* __restrict__ ws0, const float* __restrict__ ws1,
    const float* __restrict__ wc0, const float* __restrict__ wc1, const float* __restrict__ wc2,
    const float* __restrict__ wn0, const float* __restrict__ wn1,
    const float* __restrict__ wm0, const float* __restrict__ bm0,
    const float* __restrict__ wm1, const float* __restrict__ bm1,
    float* __restrict__ out, HGParams prm)
{
    const int tid = threadIdx.x;
    for (int i = tid; i < 2048; i += NTHREADS) smem[OFF_WS0 + i] = ws0[i];
    for (int i = tid; i < 2048; i += NTHREADS) { int k = i >> 5, e = i & 31; smem[OFF_WS0T + i] = ws0[e * 64 + k]; }
    for (int i = tid; i < 1024; i += NTHREADS) smem[OFF_WS1 + i] = ws1[i];
    for (int i = tid; i < 1984; i += NTHREADS) smem[OFF_WC0 + i] = wc0[i];
    for (int i = tid; i < 4096; i += NTHREADS) smem[OFF_WC1 + i] = wc1[i];
    for (int i = tid; i < 192;  i += NTHREADS) smem[OFF_WC2 + i] = wc2[i];
    for (int i = tid; i < 960;  i += NTHREADS) smem[OFF_WN0 + i] = wn0[i];
    for (int i = tid; i < 192;  i += NTHREADS) smem[OFF_WN1 + i] = wn1[i];
    for (int i = tid; i < 480;  i += NTHREADS) smem[OFF_WM0 + i] = wm0[i];
    for (int i = tid; i < 32;   i += NTHREADS) smem[OFF_WM1 + i] = wm1[i];
    for (int i = tid; i < 32;   i += NTHREADS) smem[OFF_BM0 + i] = bm0[i];
    if (tid == 0) smem[OFF_BM1] = bm1[0];
    __syncthreads();

    const int lane = tid & 31;
    const int gwarp = blockIdx.x * NWARPS_BLK + (tid >> 5);
    const int nwarp = gridDim.x * NWARPS_BLK;
    const int j16 = lane & 15;

    // lane -> (level = lane>>1, feature = lane&1)
    const int lvl = lane >> 1;
    const int feat1 = lane & 1;
    const int res = prm.res[lvl];
    const int dense = prm.dense[lvl];
    const int resm1 = res - 1;
    const float rm1 = (float)resm1;
    const float gscale = rm1 * 0.5f;
    const unsigned my = dense ? (unsigned)res : 2654435761u;
    const unsigned mz = dense ? (unsigned)(res * res) : 805459861u;
    const float2* __restrict__ tabl = ((const float2*)tables) + (size_t)lvl * TSZ;

    const float* sws0  = smem + OFF_WS0;
    const float* sws0t = smem + OFF_WS0T;
    const float* sws1  = smem + OFF_WS1;
    const float* swc0  = smem + OFF_WC0;
    const float* swc1  = smem + OFF_WC1;
    const float* swc2  = smem + OFF_WC2;
    const float* swn0  = smem + OFF_WN0;
    const float* swn1  = smem + OFF_WN1;
    const float* swm0  = smem + OFF_WM0;
    const float* swm1  = smem + OFF_WM1;
    const float* sbm0  = smem + OFF_BM0;

    for (int pbase = gwarp * (2 * NPAIR); pbase < NPTS; pbase += nwarp * (2 * NPAIR)) {
        // ================= hashgrid gather (8 points, serial) =================
        u64 encP[NPAIR], dfx[NPAIR], dfy[NPAIR], dfz[NPAIR];
        #pragma unroll
        for (int P = 0; P < NPAIR; ++P) {
            float e2[2], gx2[2], gy2[2], gz2[2];
            #pragma unroll
            for (int q = 0; q < 2; ++q) {
                const float* xp = x + (size_t)(pbase + 2 * P + q) * 6;
                float X = fminf(fmaxf((__ldg(xp + 0) + 1.0f) * 0.5f, 0.0f), 1.0f);
                float Y = fminf(fmaxf((__ldg(xp + 1) + 1.0f) * 0.5f, 0.0f), 1.0f);
                float Z = fminf(fmaxf((__ldg(xp + 2) + 1.0f) * 0.5f, 0.0f), 1.0f);
                float px = X * rm1, py = Y * rm1, pz = Z * rm1;
                float fpx = floorf(px), fpy = floorf(py), fpz = floorf(pz);
                float fx = px - fpx, fy = py - fpy, fz = pz - fpz;
                int ix = (int)fpx, iy = (int)fpy, iz = (int)fpz;
                int ix1 = min(ix + 1, resm1), iy1 = min(iy + 1, resm1), iz1 = min(iz + 1, resm1);
                unsigned ax[2] = { (unsigned)ix, (unsigned)ix1 };
                unsigned ay[2] = { (unsigned)iy * my, (unsigned)iy1 * my };
                unsigned az[2] = { (unsigned)iz * mz, (unsigned)iz1 * mz };
                float2 tv[8];
                #pragma unroll
                for (int c = 0; c < 8; ++c) {
                    int bx = (c >> 2) & 1, by = (c >> 1) & 1, bz = c & 1;
                    unsigned idx = dense ? (ax[bx] + ay[by] + az[bz])
                                         : ((ax[bx] ^ ay[by] ^ az[bz]) & (unsigned)(TSZ - 1));
                    tv[c] = __ldg(tabl + idx);
                }
                float ox = 1.f - fx, oy = 1.f - fy, oz = 1.f - fz;
                float e = 0.f, gx = 0.f, gy = 0.f, gz = 0.f;
                #pragma unroll
                for (int c = 0; c < 8; ++c) {
                    int bx = (c >> 2) & 1, by = (c >> 1) & 1, bz = c & 1;
                    float wx = bx ? fx : ox, wy = by ? fy : oy, wz = bz ? fz : oz;
                    float v = feat1 ? tv[c].y : tv[c].x;
                    float wxy = wx * wy;
                    e = fmaf(v, wxy * wz, e);
                    float vx = bx ? v : -v, vy = by ? v : -v, vz = bz ? v : -v;
                    gx = fmaf(vx, wy * wz, gx);
                    gy = fmaf(vy, wx * wz, gy);
                    gz = fmaf(vz, wxy, gz);
                }
                e2[q] = e; gx2[q] = gx * gscale; gy2[q] = gy * gscale; gz2[q] = gz * gscale;
            }
            encP[P] = pk(e2[0], e2[1]);
            dfx[P] = pk(gx2[0], gx2[1]);
            dfy[P] = pk(gy2[0], gy2[1]);
            dfz[P] = pk(gz2[0], gz2[1]);
        }

        // ================= density layer0: h1[64] = relu(enc @ ws0) =================
        u64 h1[NPAIR][2];
        #pragma unroll
        for (int P = 0; P < NPAIR; ++P) { h1[P][0] = 0ull; h1[P][1] = 0ull; }
        #pragma unroll 4
        for (int i = 0; i < 32; ++i) {
            u64 w0 = bc2(sws0[i * 64 + lane]);
            u64 w1 = bc2(sws0[i * 64 + lane + 32]);
            #pragma unroll
            for (int P = 0; P < NPAIR; ++P) {
                u64 e = __shfl_sync(FULL, encP[P], i);
                h1[P][0] = fma2(e, w0, h1[P][0]);
                h1[P][1] = fma2(e, w1, h1[P][1]);
            }
        }
        #pragma unroll
        for (int P = 0; P < NPAIR; ++P) { h1[P][0] = relu2(h1[P][0]); h1[P][1] = relu2(h1[P][1]); }

        // ======== fused layer1 (geo = h1@ws1) + backward (genc = ws0 @ dh) ========
        // dh[k] = (pre_k>0) * ws1[k,0]; post-relu h1>0 <=> pre>0.
        u64 geo[NPAIR], genc[NPAIR];
        #pragma unroll
        for (int P = 0; P < NPAIR; ++P) { geo[P] = 0ull; genc[P] = 0ull; }
        #pragma unroll 2
        for (int kk = 0; kk < 32; ++kk) {
            u64 wA = bc2(sws1[kk * 16 + j16]);
            u64 wB = bc2(sws1[(kk + 32) * 16 + j16]);
            float m0 = sws1[kk * 16];
            float m1 = sws1[(kk + 32) * 16];
            u64 wsA = bc2(sws0t[kk * 32 + lane]);
            u64 wsB = bc2(sws0t[(kk + 32) * 32 + lane]);
            #pragma unroll
            for (int P = 0; P < NPAIR; ++P) {
                u64 a = __shfl_sync(FULL, h1[P][0], kk);
                u64 b = __shfl_sync(FULL, h1[P][1], kk);
                geo[P] = fma2(a, wA, fma2(b, wB, geo[P]));
                float alo, ahi, blo, bhi; upk(a, alo, ahi); upk(b, blo, bhi);
                u64 da = pk(alo > 0.f ? m0 : 0.f, ahi > 0.f ? m0 : 0.f);
                u64 db = pk(blo > 0.f ? m1 : 0.f, bhi > 0.f ? m1 : 0.f);
                genc[P] = fma2(da, wsA, fma2(db, wsB, genc[P]));
            }
        }

        // ================= normal = l2norm(-grad) =================
        #pragma unroll
        for (int P = 0; P < NPAIR; ++P) {
            u64 sx = allsum2(mul2(genc[P], dfx[P]));
            u64 sy = allsum2(mul2(genc[P], dfy[P]));
            u64 sz = allsum2(mul2(genc[P], dfz[P]));
            float nx0, nx1, ny0, ny1, nz0, nz1;
            upk(sx, nx0, nx1); upk(sy, ny0, ny1); upk(sz, nz0, nz1);
            #pragma unroll
            for (int q = 0; q < 2; ++q) {
                float n0 = -(q ? nx1 : nx0), n1 = -(q ? ny1 : ny0), n2 = -(q ? nz1 : nz0);
                float inv = 1.0f / fmaxf(sqrtf(n0 * n0 + n1 * n1 + n2 * n2), 1e-8f);
                if (lane < 3)
                    out[(size_t)NPTS * 16 + (size_t)(pbase + P * 2 + q) * 3 + lane] =
                        sel3(lane, n0 * inv, n1 * inv, n2 * inv);
            }
        }

        // ================= pred_normal =================
        {
            u64 t0[NPAIR], t1[NPAIR];
            #pragma unroll
            for (int P = 0; P < NPAIR; ++P) { t0[P] = 0ull; t1[P] = 0ull; }
            #pragma unroll
            for (int i = 0; i < 15; ++i) {
                u64 w0 = bc2(swn0[i * 64 + lane]);
                u64 w1 = bc2(swn0[i * 64 + lane + 32]);
                #pragma unroll
                for (int P = 0; P < NPAIR; ++P) {
                    u64 g = __shfl_sync(FULL, geo[P], i + 1);
                    t0[P] = fma2(g, w0, t0[P]);
                    t1[P] = fma2(g, w1, t1[P]);
                }
            }
            #pragma unroll
            for (int P = 0; P < NPAIR; ++P) { t0[P] = relu2(t0[P]); t1[P] = relu2(t1[P]); }
            #pragma unroll
            for (int P = 0; P < NPAIR; ++P) {
                float pn[3][2];
                #pragma unroll
                for (int d = 0; d < 3; ++d) {
                    u64 wA = bc2(swn1[lane * 3 + d]);
                    u64 wB = bc2(swn1[(lane + 32) * 3 + d]);
                    u64 s = allsum2(fma2(t0[P], wA, mul2(t1[P], wB)));
                    upk(s, pn[d][0], pn[d][1]);
                }
                #pragma unroll
                for (int q = 0; q < 2; ++q) {
                    float n0 = pn[0][q], n1 = pn[1][q], n2 = pn[2][q];
                    float inv = 1.0f / fmaxf(sqrtf(n0 * n0 + n1 * n1 + n2 * n2), 1e-8f);
                    if (lane < 3)
                        out[(size_t)NPTS * 19 + (size_t)(pbase + P * 2 + q) * 3 + lane] =
                            sel3(lane, n0 * inv, n1 * inv, n2 * inv);
                }
            }
        }

        // ================= color =================
        {
            u64 ca[NPAIR], cb[NPAIR];
            // geo part of wc0 (rows 16..30), amortized across pairs
            #pragma unroll
            for (int P = 0; P < NPAIR; ++P) { ca[P] = 0ull; cb[P] = 0ull; }
            #pragma unroll
            for (int i = 0; i < 15; ++i) {
                u64 w0 = bc2(swc0[(16 + i) * 64 + lane]);
                u64 w1 = bc2(swc0[(16 + i) * 64 + lane + 32]);
                #pragma unroll
                for (int P = 0; P < NPAIR; ++P) {
                    u64 g = __shfl_sync(FULL, geo[P], i + 1);
                    ca[P] = fma2(g, w0, ca[P]);
                    cb[P] = fma2(g, w1, cb[P]);
                }
            }
            // SH part per pair (reload dir from x)
            #pragma unroll
            for (int P = 0; P < NPAIR; ++P) {
                const float* xp0 = x + (size_t)(pbase + 2 * P) * 6;
                const float* xp1 = x + (size_t)(pbase + 2 * P + 1) * 6;
                u64 X = pk(__ldg(xp0 + 3), __ldg(xp1 + 3));
                u64 Y = pk(__ldg(xp0 + 4), __ldg(xp1 + 4));
                u64 Z = pk(__ldg(xp0 + 5), __ldg(xp1 + 5));
                u64 XY = mul2(X, Y), XZ = mul2(X, Z), YZ = mul2(Y, Z);
                u64 X2 = mul2(X, X), Y2 = mul2(Y, Y), Z2 = mul2(Z, Z);
                u64 shp[16];
                shp[0] = bc2(0.28209479177387814f);
                shp[1] = mul2(bc2(-0.48860251190291987f), Y);
                shp[2] = mul2(bc2(0.48860251190291987f), Z);
                shp[3] = mul2(bc2(-0.48860251190291987f), X);
                shp[4] = mul2(bc2(1.0925484305920792f), XY);
                shp[5] = mul2(bc2(-1.0925484305920792f), YZ);
                shp[6] = fma2(bc2(0.94617469575756f), Z2, bc2(-0.31539156525252005f));
                shp[7] = mul2(bc2(-1.0925484305920792f), XZ);
                shp[8] = mul2(bc2(0.5462742152960396f), fma2(Y2, bc2(-1.f), X2));
                shp[9] = mul2(bc2(0.5900435899266435f), mul2(Y, fma2(bc2(-3.f), X2, Y2)));
                shp[10] = mul2(bc2(2.890611442640554f), mul2(XY, Z));
                shp[11] = mul2(bc2(0.4570457994644657f), mul2(Y, fma2(bc2(-5.f), Z2, bc2(1.f))));
                shp[12] = mul2(bc2(0.3731763325901154f), mul2(Z, fma2(bc2(5.f), Z2, bc2(-3.f))));
                shp[13] = mul2(bc2(0.4570457994644657f), mul2(X, fma2(bc2(-5.f), Z2, bc2(1.f))));
                shp[14] = mul2(bc2(1.445305721320277f), mul2(Z, fma2(Y2, bc2(-1.f), X2)));
                shp[15] = mul2(bc2(0.5900435899266435f), mul2(X, fma2(bc2(-3.f), Y2, X2)));
                #pragma unroll
                for (int i = 0; i < 16; ++i) {
                    ca[P] = fma2(shp[i], bc2(swc0[i * 64 + lane]), ca[P]);
                    cb[P] = fma2(shp[i], bc2(swc0[i * 64 + lane + 32]), cb[P]);
                }
                ca[P] = relu2(ca[P]); cb[P] = relu2(cb[P]);
            }
            // layer wc1
            u64 c10[NPAIR], c11[NPAIR];
            #pragma unroll
            for (int P = 0; P < NPAIR; ++P) { c10[P] = 0ull; c11[P] = 0ull; }
            #pragma unroll 2
            for (int kk = 0; kk < 32; ++kk) {
                u64 w00 = bc2(swc1[kk * 64 + lane]);
                u64 w01 = bc2(swc1[kk * 64 + lane + 32]);
                u64 w10 = bc2(swc1[(kk + 32) * 64 + lane]);
                u64 w11 = bc2(swc1[(kk + 32) * 64 + lane + 32]);
                #pragma unroll
                for (int P = 0; P < NPAIR; ++P) {
                    u64 hA = __shfl_sync(FULL, ca[P], kk);
                    u64 hB = __shfl_sync(FULL, cb[P], kk);
                    c10[P] = fma2(hA, w00, fma2(hB, w10, c10[P]));
                    c11[P] = fma2(hA, w01, fma2(hB, w11, c11[P]));
                }
            }
            #pragma unroll
            for (int P = 0; P < NPAIR; ++P) { c10[P] = relu2(c10[P]); c11[P] = relu2(c11[P]); }
            #pragma unroll
            for (int d = 0; d < 3; ++d) {
                u64 wA = bc2(swc2[lane * 3 + d]);
                u64 wB = bc2(swc2[(lane + 32) * 3 + d]);
                #pragma unroll
                for (int P = 0; P < NPAIR; ++P) {
                    u64 s = allsum2(fma2(c10[P], wA, mul2(c11[P], wB)));
                    float r0, r1; upk(s, r0, r1);
                    if (lane == d) {
                        out[(size_t)NPTS * 22 + (size_t)(pbase + P * 2 + 0) * 3 + d] = sigm(r0);
                        out[(size_t)NPTS * 22 + (size_t)(pbase + P * 2 + 1) * 3 + d] = sigm(r1);
                    }
                }
            }
        }

        // ================= mirror head =================
        {
            u64 m[NPAIR];
            #pragma unroll
            for (int P = 0; P < NPAIR; ++P) m[P] = bc2(sbm0[lane]);
            #pragma unroll
            for (int i = 0; i < 15; ++i) {
                u64 w = bc2(swm0[i * 32 + lane]);
                #pragma unroll
                for (int P = 0; P < NPAIR; ++P) {
                    u64 g = __shfl_sync(FULL, geo[P], i + 1);
                    m[P] = fma2(g, w, m[P]);
                }
            }
            float bm1v = smem[OFF_BM1];
            u64 wv = bc2(swm1[lane]);
            #pragma unroll
            for (int P = 0; P < NPAIR; ++P) {
                float a, b; upk(m[P], a, b);
                a = a > 0.f ? a : 0.01f * a;
                b = b > 0.f ? b : 0.01f * b;
                u64 s = allsum2(mul2(pk(a, b), wv));
                float s0, s1; upk(s, s0, s1);
                if (lane == 0) {
                    out[(size_t)NPTS * 25 + (pbase + P * 2 + 0)] = sigm(s0 + bm1v);
                    out[(size_t)NPTS * 25 + (pbase + P * 2 + 1)] = sigm(s1 + bm1v);
                }
            }
        }

        // ================= sigma + geo_feat =================
        #pragma unroll
        for (int P = 0; P < NPAIR; ++P) {
            float gA, gB; upk(geo[P], gA, gB);
            size_t p0 = (size_t)(pbase + P * 2), p1 = p0 + 1;
            if (lane == 0) { out[p0] = gA; out[p1] = gB; }
            if (lane >= 1 && lane < 16) {
                out[(size_t)NPTS + p0 * 15 + (lane - 1)] = gA;
                out[(size_t)NPTS + p1 * 15 + (lane - 1)] = gB;
            }
        }
    }
}

extern "C" void kernel_launch(void* const* d_in, const int* in_sizes, int n_in,
                              void* d_out, int out_size) {
    (void)in_sizes; (void)n_in; (void)out_size;
    HGParams prm;
    double pls = exp2(log2(2048.0 * 1.0 / 16.0) / 15.0);
    for (int l = 0; l < 16; ++l) {
        int r = (int)floor(16.0 * pow(pls, (double)l));
        prm.res[l] = r;
        long long r3 = (long long)r * r * r;
        prm.dense[l] = (r3 <= (long long)TSZ) ? 1 : 0;
    }
    size_t smemBytes = (size_t)SMEM_FLOATS * sizeof(float);
    cudaFuncSetAttribute(nerf_kernel, cudaFuncAttributeMaxDynamicSharedMemorySize, (int)smemBytes);
    nerf_kernel<<<NBLOCKS, NTHREADS, smemBytes>>>(
        (const float*)d_in[0], (const float*)d_in[1],
        (const float*)d_in[2], (const float*)d_in[3],
        (const float*)d_in[4], (const float*)d_in[5], (const float*)d_in[6],
        (const float*)d_in[7], (const float*)d_in[8],
        (const float*)d_in[9], (const float*)d_in[10],
        (const float*)d_in[11], (const float*)d_in[12],
        (float*)d_out, prm);
}

// round 4
// speedup vs baseline: 1.5118x; 1.0997x over previous
#include <cuda_runtime.h>
#include <math.h>
#include <stdint.h>

#define NPTS 524288
#define TSZ  524288
#define NTHREADS 256
#define NWARPS_BLK 8
#define NBLOCKS 296
#define FULL 0xffffffffu
#define NPAIR 4   // 8 points per warp iteration

typedef unsigned long long u64;

// ---- shared memory layout (float offsets) ----
#define OFF_WS0PK   0       // [32][32] float2
#define OFF_WS0TPK  2048    // [32][32] float2
#define OFF_WS1PK   4096    // [32][16] float2
#define OFF_WC1PK   5120    // [32][32] float4
#define OFF_WC0PK   9216    // [31][32] float2
#define OFF_WN0PK   11200   // [15][32] float2
#define OFF_WC2     12160   // [64][3]
#define OFF_WN1     12352   // [64][3]
#define OFF_WM0     12544   // [15][32]
#define OFF_WM1     13024   // [32]
#define OFF_BM0     13056   // [32]
#define OFF_BM1     13088   // [1]
#define OFF_DF      13090   // 8 warps * 384 u64 (12 u64 per lane)
#define SMEM_FLOATS (13090 + NWARPS_BLK * 768)

struct HGParams { int res[16]; int dense[16]; };

__device__ __forceinline__ u64 pk(float lo, float hi) {
    u64 r; asm("mov.b64 %0,{%1,%2};" : "=l"(r) : "f"(lo), "f"(hi)); return r;
}
__device__ __forceinline__ void upk(u64 v, float& lo, float& hi) {
    asm("mov.b64 {%0,%1},%2;" : "=f"(lo), "=f"(hi) : "l"(v));
}
__device__ __forceinline__ u64 bc2(float w) { return pk(w, w); }
__device__ __forceinline__ u64 fma2(u64 a, u64 b, u64 c) {
    u64 d; asm("fma.rn.f32x2 %0,%1,%2,%3;" : "=l"(d) : "l"(a), "l"(b), "l"(c)); return d;
}
__device__ __forceinline__ u64 mul2(u64 a, u64 b) {
    u64 d; asm("mul.rn.f32x2 %0,%1,%2;" : "=l"(d) : "l"(a), "l"(b)); return d;
}
__device__ __forceinline__ u64 add2(u64 a, u64 b) {
    u64 d; asm("add.rn.f32x2 %0,%1,%2;" : "=l"(d) : "l"(a), "l"(b)); return d;
}
__device__ __forceinline__ u64 relu2(u64 v) {
    float a, b; upk(v, a, b); return pk(fmaxf(a, 0.f), fmaxf(b, 0.f));
}
__device__ __forceinline__ u64 allsum2(u64 v) {
    #pragma unroll
    for (int o = 16; o > 0; o >>= 1) v = add2(v, __shfl_xor_sync(FULL, v, o));
    return v;
}
__device__ __forceinline__ float sigm(float v) { return 1.0f / (1.0f + expf(-v)); }
__device__ __forceinline__ float sel3(int lane, float a, float b, float c) {
    return lane == 0 ? a : (lane == 1 ? b : c);
}

extern __shared__ float smem[];

__global__ __launch_bounds__(NTHREADS, 2) void nerf_kernel(
    const float* __restrict__ x,
    const float* __restrict__ tables,
    const float* __restrict__ ws0, const float* __restrict__ ws1,
    const float* __restrict__ wc0, const float* __restrict__ wc1, const float* __restrict__ wc2,
    const float* __restrict__ wn0, const float* __restrict__ wn1,
    const float* __restrict__ wm0, const float* __restrict__ bm0,
    const float* __restrict__ wm1, const float* __restrict__ bm1,
    float* __restrict__ out, HGParams prm)
{
    const int tid = threadIdx.x;
    // ---- stage packed weights ----
    {
        float2* p = (float2*)(smem + OFF_WS0PK);
        for (int i = tid; i < 1024; i += NTHREADS) { int r = i >> 5, c = i & 31; p[i] = make_float2(ws0[r * 64 + c], ws0[r * 64 + c + 32]); }
        float2* pt_ = (float2*)(smem + OFF_WS0TPK);
        for (int i = tid; i < 1024; i += NTHREADS) { int kk = i >> 5, c = i & 31; pt_[i] = make_float2(ws0[c * 64 + kk], ws0[c * 64 + kk + 32]); }
        float2* p1 = (float2*)(smem + OFF_WS1PK);
        for (int i = tid; i < 512; i += NTHREADS) { int kk = i >> 4, j = i & 15; p1[i] = make_float2(ws1[kk * 16 + j], ws1[(kk + 32) * 16 + j]); }
        float4* pc1 = (float4*)(smem + OFF_WC1PK);
        for (int i = tid; i < 1024; i += NTHREADS) { int kk = i >> 5, c = i & 31;
            pc1[i] = make_float4(wc1[kk * 64 + c], wc1[kk * 64 + c + 32], wc1[(kk + 32) * 64 + c], wc1[(kk + 32) * 64 + c + 32]); }
        float2* pc0 = (float2*)(smem + OFF_WC0PK);
        for (int i = tid; i < 992; i += NTHREADS) { int r = i >> 5, c = i & 31; pc0[i] = make_float2(wc0[r * 64 + c], wc0[r * 64 + c + 32]); }
        float2* pn0 = (float2*)(smem + OFF_WN0PK);
        for (int i = tid; i < 480; i += NTHREADS) { int r = i >> 5, c = i & 31; pn0[i] = make_float2(wn0[r * 64 + c], wn0[r * 64 + c + 32]); }
        for (int i = tid; i < 192; i += NTHREADS) smem[OFF_WC2 + i] = wc2[i];
        for (int i = tid; i < 192; i += NTHREADS) smem[OFF_WN1 + i] = wn1[i];
        for (int i = tid; i < 480; i += NTHREADS) smem[OFF_WM0 + i] = wm0[i];
        for (int i = tid; i < 32;  i += NTHREADS) smem[OFF_WM1 + i] = wm1[i];
        for (int i = tid; i < 32;  i += NTHREADS) smem[OFF_BM0 + i] = bm0[i];
        if (tid == 0) smem[OFF_BM1] = bm1[0];
    }
    __syncthreads();

    const int lane = tid & 31;
    const int warpInBlk = tid >> 5;
    const int gwarp = blockIdx.x * NWARPS_BLK + warpInBlk;
    const int nwarp = gridDim.x * NWARPS_BLK;
    const int j16 = lane & 15;

    // lane -> (level = lane>>1, half = bx = lane&1); lane owns feature = lane&1
    const int lvl = lane >> 1;
    const int half = lane & 1;
    const float sxsign = half ? 1.f : -1.f;
    const int res = prm.res[lvl];
    const int dense = prm.dense[lvl];
    const int resm1 = res - 1;
    const float rm1 = (float)resm1;
    const float gscale = rm1 * 0.5f;
    const unsigned my = dense ? (unsigned)res : 2654435761u;
    const unsigned mz = dense ? (unsigned)(res * res) : 805459861u;
    const float2* __restrict__ tabl = ((const float2*)tables) + (size_t)lvl * TSZ;

    const float2* ws0pk  = (const float2*)(smem + OFF_WS0PK);
    const float2* ws0tpk = (const float2*)(smem + OFF_WS0TPK);
    const float2* ws1pk  = (const float2*)(smem + OFF_WS1PK);
    const float4* wc1pk  = (const float4*)(smem + OFF_WC1PK);
    const float2* wc0pk  = (const float2*)(smem + OFF_WC0PK);
    const float2* wn0pk  = (const float2*)(smem + OFF_WN0PK);
    const float* swc2 = smem + OFF_WC2;
    const float* swn1 = smem + OFF_WN1;
    const float* swm0 = smem + OFF_WM0;
    const float* swm1 = smem + OFF_WM1;
    const float* sbm0 = smem + OFF_BM0;
    u64* dfw = ((u64*)(smem + OFF_DF)) + warpInBlk * 384;   // [P*3+d][lane]

    for (int pbase = gwarp * (2 * NPAIR); pbase < NPTS; pbase += nwarp * (2 * NPAIR)) {
        // ================= hashgrid gather (8 points; 4 corners/lane) =================
        u64 encP[NPAIR];
        #pragma unroll
        for (int P = 0; P < NPAIR; ++P) {
            float e2[2], gx2[2], gy2[2], gz2[2];
            #pragma unroll
            for (int q = 0; q < 2; ++q) {
                const float* xp = x + (size_t)(pbase + 2 * P + q) * 6;
                float X = fminf(fmaxf((__ldg(xp + 0) + 1.0f) * 0.5f, 0.0f), 1.0f);
                float Y = fminf(fmaxf((__ldg(xp + 1) + 1.0f) * 0.5f, 0.0f), 1.0f);
                float Z = fminf(fmaxf((__ldg(xp + 2) + 1.0f) * 0.5f, 0.0f), 1.0f);
                float px = X * rm1, py = Y * rm1, pz = Z * rm1;
                float fpx = floorf(px), fpy = floorf(py), fpz = floorf(pz);
                float fx = px - fpx, fy = py - fpy, fz = pz - fpz;
                int ix = (int)fpx, iy = (int)fpy, iz = (int)fpz;
                int ix1 = min(ix + 1, resm1), iy1 = min(iy + 1, resm1), iz1 = min(iz + 1, resm1);
                unsigned tx = half ? (unsigned)ix1 : (unsigned)ix;
                unsigned ay[2] = { (unsigned)iy * my, (unsigned)iy1 * my };
                unsigned az[2] = { (unsigned)iz * mz, (unsigned)iz1 * mz };
                float2 tv[4];
                #pragma unroll
                for (int j = 0; j < 4; ++j) {
                    int by = j >> 1, bz = j & 1;
                    unsigned idx = dense ? (tx + ay[by] + az[bz])
                                         : ((tx ^ ay[by] ^ az[bz]) & (unsigned)(TSZ - 1));
                    tv[j] = __ldg(tabl + idx);
                }
                float oy = 1.f - fy, oz = 1.f - fz;
                float S0 = 0.f, S1 = 0.f, Sy0 = 0.f, Sy1 = 0.f, Sz0 = 0.f, Sz1 = 0.f;
                #pragma unroll
                for (int j = 0; j < 4; ++j) {
                    int by = j >> 1, bz = j & 1;
                    float wy = by ? fy : oy, wz = bz ? fz : oz;
                    float wyz = wy * wz;
                    S0 = fmaf(tv[j].x, wyz, S0);  S1 = fmaf(tv[j].y, wyz, S1);
                    float syw = by ? wz : -wz;
                    Sy0 = fmaf(tv[j].x, syw, Sy0); Sy1 = fmaf(tv[j].y, syw, Sy1);
                    float szw = bz ? wy : -wy;
                    Sz0 = fmaf(tv[j].x, szw, Sz0); Sz1 = fmaf(tv[j].y, szw, Sz1);
                }
                float wxc = half ? fx : 1.f - fx;
                // own feature = half; partner feature partials to exchange
                float So  = half ? S1 : S0,  Sp  = half ? S0 : S1;
                float Syo = half ? Sy1 : Sy0, Syp = half ? Sy0 : Sy1;
                float Szo = half ? Sz1 : Sz0, Szp = half ? Sz0 : Sz1;
                u64 A = __shfl_xor_sync(FULL, pk(wxc * Sp, sxsign * Sp), 1);
                u64 B = __shfl_xor_sync(FULL, pk(wxc * Syp, wxc * Szp), 1);
                float er, gxr, gyr, gzr;
                upk(A, er, gxr); upk(B, gyr, gzr);
                e2[q]  = fmaf(wxc, So, er);
                gx2[q] = (fmaf(sxsign, So, gxr)) * gscale;
                gy2[q] = (fmaf(wxc, Syo, gyr)) * gscale;
                gz2[q] = (fmaf(wxc, Szo, gzr)) * gscale;
            }
            encP[P] = pk(e2[0], e2[1]);
            dfw[(P * 3 + 0) * 32 + lane] = pk(gx2[0], gx2[1]);
            dfw[(P * 3 + 1) * 32 + lane] = pk(gy2[0], gy2[1]);
            dfw[(P * 3 + 2) * 32 + lane] = pk(gz2[0], gz2[1]);
        }

        // ================= density layer0: h1[64] = relu(enc @ ws0) =================
        u64 h1[NPAIR][2];
        #pragma unroll
        for (int P = 0; P < NPAIR; ++P) { h1[P][0] = 0ull; h1[P][1] = 0ull; }
        #pragma unroll 4
        for (int i = 0; i < 32; ++i) {
            float2 w = ws0pk[i * 32 + lane];
            u64 w0 = bc2(w.x), w1 = bc2(w.y);
            #pragma unroll
            for (int P = 0; P < NPAIR; ++P) {
                u64 e = __shfl_sync(FULL, encP[P], i);
                h1[P][0] = fma2(e, w0, h1[P][0]);
                h1[P][1] = fma2(e, w1, h1[P][1]);
            }
        }
        #pragma unroll
        for (int P = 0; P < NPAIR; ++P) { h1[P][0] = relu2(h1[P][0]); h1[P][1] = relu2(h1[P][1]); }

        // ======== fused layer1 (geo = h1@ws1) + backward (genc = ws0 @ dh) ========
        u64 geo[NPAIR], genc[NPAIR];
        #pragma unroll
        for (int P = 0; P < NPAIR; ++P) { geo[P] = 0ull; genc[P] = 0ull; }
        #pragma unroll 2
        for (int kk = 0; kk < 32; ++kk) {
            float2 wab = ws1pk[kk * 16 + j16];
            float2 m01 = ws1pk[kk * 16];
            float2 wst = ws0tpk[kk * 32 + lane];
            u64 wA = bc2(wab.x), wB = bc2(wab.y);
            u64 wsA = bc2(wst.x), wsB = bc2(wst.y);
            #pragma unroll
            for (int P = 0; P < NPAIR; ++P) {
                u64 a = __shfl_sync(FULL, h1[P][0], kk);
                u64 b = __shfl_sync(FULL, h1[P][1], kk);
                geo[P] = fma2(a, wA, fma2(b, wB, geo[P]));
                float alo, ahi, blo, bhi; upk(a, alo, ahi); upk(b, blo, bhi);
                u64 da = pk(alo > 0.f ? m01.x : 0.f, ahi > 0.f ? m01.x : 0.f);
                u64 db = pk(blo > 0.f ? m01.y : 0.f, bhi > 0.f ? m01.y : 0.f);
                genc[P] = fma2(da, wsA, fma2(db, wsB, genc[P]));
            }
        }

        // ================= normal = l2norm(-grad) =================
        #pragma unroll
        for (int P = 0; P < NPAIR; ++P) {
            u64 sx = allsum2(mul2(genc[P], dfw[(P * 3 + 0) * 32 + lane]));
            u64 sy = allsum2(mul2(genc[P], dfw[(P * 3 + 1) * 32 + lane]));
            u64 sz = allsum2(mul2(genc[P], dfw[(P * 3 + 2) * 32 + lane]));
            float nx0, nx1, ny0, ny1, nz0, nz1;
            upk(sx, nx0, nx1); upk(sy, ny0, ny1); upk(sz, nz0, nz1);
            #pragma unroll
            for (int q = 0; q < 2; ++q) {
                float n0 = -(q ? nx1 : nx0), n1 = -(q ? ny1 : ny0), n2 = -(q ? nz1 : nz0);
                float inv = 1.0f / fmaxf(sqrtf(n0 * n0 + n1 * n1 + n2 * n2), 1e-8f);
                if (lane < 3)
                    out[(size_t)NPTS * 16 + (size_t)(pbase + P * 2 + q) * 3 + lane] =
                        sel3(lane, n0 * inv, n1 * inv, n2 * inv);
            }
        }

        // ================= pred_normal =================
        {
            u64 t0[NPAIR], t1[NPAIR];
            #pragma unroll
            for (int P = 0; P < NPAIR; ++P) { t0[P] = 0ull; t1[P] = 0ull; }
            #pragma unroll
            for (int i = 0; i < 15; ++i) {
                float2 w = wn0pk[i * 32 + lane];
                u64 w0 = bc2(w.x), w1 = bc2(w.y);
                #pragma unroll
                for (int P = 0; P < NPAIR; ++P) {
                    u64 g = __shfl_sync(FULL, geo[P], i + 1);
                    t0[P] = fma2(g, w0, t0[P]);
                    t1[P] = fma2(g, w1, t1[P]);
                }
            }
            #pragma unroll
            for (int P = 0; P < NPAIR; ++P) { t0[P] = relu2(t0[P]); t1[P] = relu2(t1[P]); }
            #pragma unroll
            for (int P = 0; P < NPAIR; ++P) {
                float pn[3][2];
                #pragma unroll
                for (int d = 0; d < 3; ++d) {
                    u64 wA = bc2(swn1[lane * 3 + d]);
                    u64 wB = bc2(swn1[(lane + 32) * 3 + d]);
                    u64 s = allsum2(fma2(t0[P], wA, mul2(t1[P], wB)));
                    upk(s, pn[d][0], pn[d][1]);
                }
                #pragma unroll
                for (int q = 0; q < 2; ++q) {
                    float n0 = pn[0][q], n1 = pn[1][q], n2 = pn[2][q];
                    float inv = 1.0f / fmaxf(sqrtf(n0 * n0 + n1 * n1 + n2 * n2), 1e-8f);
                    if (lane < 3)
                        out[(size_t)NPTS * 19 + (size_t)(pbase + P * 2 + q) * 3 + lane] =
                            sel3(lane, n0 * inv, n1 * inv, n2 * inv);
                }
            }
        }

        // ================= color =================
        {
            u64 ca[NPAIR], cb[NPAIR];
            #pragma unroll
            for (int P = 0; P < NPAIR; ++P) { ca[P] = 0ull; cb[P] = 0ull; }
            #pragma unroll
            for (int i = 0; i < 15; ++i) {
                float2 w = wc0pk[(16 + i) * 32 + lane];
                u64 w0 = bc2(w.x), w1 = bc2(w.y);
                #pragma unroll
                for (int P = 0; P < NPAIR; ++P) {
                    u64 g = __shfl_sync(FULL, geo[P], i + 1);
                    ca[P] = fma2(g, w0, ca[P]);
                    cb[P] = fma2(g, w1, cb[P]);
                }
            }
            #pragma unroll
            for (int P = 0; P < NPAIR; ++P) {
                const float* xp0 = x + (size_t)(pbase + 2 * P) * 6;
                const float* xp1 = x + (size_t)(pbase + 2 * P + 1) * 6;
                u64 X = pk(__ldg(xp0 + 3), __ldg(xp1 + 3));
                u64 Y = pk(__ldg(xp0 + 4), __ldg(xp1 + 4));
                u64 Z = pk(__ldg(xp0 + 5), __ldg(xp1 + 5));
                u64 XY = mul2(X, Y), XZ = mul2(X, Z), YZ = mul2(Y, Z);
                u64 X2 = mul2(X, X), Y2 = mul2(Y, Y), Z2 = mul2(Z, Z);
                u64 shp[16];
                shp[0] = bc2(0.28209479177387814f);
                shp[1] = mul2(bc2(-0.48860251190291987f), Y);
                shp[2] = mul2(bc2(0.48860251190291987f), Z);
                shp[3] = mul2(bc2(-0.48860251190291987f), X);
                shp[4] = mul2(bc2(1.0925484305920792f), XY);
                shp[5] = mul2(bc2(-1.0925484305920792f), YZ);
                shp[6] = fma2(bc2(0.94617469575756f), Z2, bc2(-0.31539156525252005f));
                shp[7] = mul2(bc2(-1.0925484305920792f), XZ);
                shp[8] = mul2(bc2(0.5462742152960396f), fma2(Y2, bc2(-1.f), X2));
                shp[9] = mul2(bc2(0.5900435899266435f), mul2(Y, fma2(bc2(-3.f), X2, Y2)));
                shp[10] = mul2(bc2(2.890611442640554f), mul2(XY, Z));
                shp[11] = mul2(bc2(0.4570457994644657f), mul2(Y, fma2(bc2(-5.f), Z2, bc2(1.f))));
                shp[12] = mul2(bc2(0.3731763325901154f), mul2(Z, fma2(bc2(5.f), Z2, bc2(-3.f))));
                shp[13] = mul2(bc2(0.4570457994644657f), mul2(X, fma2(bc2(-5.f), Z2, bc2(1.f))));
                shp[14] = mul2(bc2(1.445305721320277f), mul2(Z, fma2(Y2, bc2(-1.f), X2)));
                shp[15] = mul2(bc2(0.5900435899266435f), mul2(X, fma2(bc2(-3.f), Y2, X2)));
                #pragma unroll
                for (int i = 0; i < 16; ++i) {
                    float2 w = wc0pk[i * 32 + lane];
                    ca[P] = fma2(shp[i], bc2(w.x), ca[P]);
                    cb[P] = fma2(shp[i], bc2(w.y), cb[P]);
                }
                ca[P] = relu2(ca[P]); cb[P] = relu2(cb[P]);
            }
            u64 c10[NPAIR], c11[NPAIR];
            #pragma unroll
            for (int P = 0; P < NPAIR; ++P) { c10[P] = 0ull; c11[P] = 0ull; }
            #pragma unroll 2
            for (int kk = 0; kk < 32; ++kk) {
                float4 w4 = wc1pk[kk * 32 + lane];
                u64 w00 = bc2(w4.x), w01 = bc2(w4.y), w10 = bc2(w4.z), w11 = bc2(w4.w);
                #pragma unroll
                for (int P = 0; P < NPAIR; ++P) {
                    u64 hA = __shfl_sync(FULL, ca[P], kk);
                    u64 hB = __shfl_sync(FULL, cb[P], kk);
                    c10[P] = fma2(hA, w00, fma2(hB, w10, c10[P]));
                    c11[P] = fma2(hA, w01, fma2(hB, w11, c11[P]));
                }
            }
            #pragma unroll
            for (int P = 0; P < NPAIR; ++P) { c10[P] = relu2(c10[P]); c11[P] = relu2(c11[P]); }
            #pragma unroll
            for (int d = 0; d < 3; ++d) {
                u64 wA = bc2(swc2[lane * 3 + d]);
                u64 wB = bc2(swc2[(lane + 32) * 3 + d]);
                #pragma unroll
                for (int P = 0; P < NPAIR; ++P) {
                    u64 s = allsum2(fma2(c10[P], wA, mul2(c11[P], wB)));
                    float r0, r1; upk(s, r0, r1);
                    if (lane == d) {
                        out[(size_t)NPTS * 22 + (size_t)(pbase + P * 2 + 0) * 3 + d] = sigm(r0);
                        out[(size_t)NPTS * 22 + (size_t)(pbase + P * 2 + 1) * 3 + d] = sigm(r1);
                    }
                }
            }
        }

        // ================= mirror head =================
        {
            u64 m[NPAIR];
            #pragma unroll
            for (int P = 0; P < NPAIR; ++P) m[P] = bc2(sbm0[lane]);
            #pragma unroll
            for (int i = 0; i < 15; ++i) {
                u64 w = bc2(swm0[i * 32 + lane]);
                #pragma unroll
                for (int P = 0; P < NPAIR; ++P) {
                    u64 g = __shfl_sync(FULL, geo[P], i + 1);
                    m[P] = fma2(g, w, m[P]);
                }
            }
            float bm1v = smem[OFF_BM1];
            u64 wv = bc2(swm1[lane]);
            #pragma unroll
            for (int P = 0; P < NPAIR; ++P) {
                float a, b; upk(m[P], a, b);
                a = a > 0.f ? a : 0.01f * a;
                b = b > 0.f ? b : 0.01f * b;
                u64 s = allsum2(mul2(pk(a, b), wv));
                float s0, s1; upk(s, s0, s1);
                if (lane == 0) {
                    out[(size_t)NPTS * 25 + (pbase + P * 2 + 0)] = sigm(s0 + bm1v);
                    out[(size_t)NPTS * 25 + (pbase + P * 2 + 1)] = sigm(s1 + bm1v);
                }
            }
        }

        // ================= sigma + geo_feat =================
        #pragma unroll
        for (int P = 0; P < NPAIR; ++P) {
            float gA, gB; upk(geo[P], gA, gB);
            size_t p0 = (size_t)(pbase + P * 2), p1 = p0 + 1;
            if (lane == 0) { out[p0] = gA; out[p1] = gB; }
            if (lane >= 1 && lane < 16) {
                out[(size_t)NPTS + p0 * 15 + (lane - 1)] = gA;
                out[(size_t)NPTS + p1 * 15 + (lane - 1)] = gB;
            }
        }
    }
}

extern "C" void kernel_launch(void* const* d_in, const int* in_sizes, int n_in,
                              void* d_out, int out_size) {
    (void)in_sizes; (void)n_in; (void)out_size;
    HGParams prm;
    double pls = exp2(log2(2048.0 * 1.0 / 16.0) / 15.0);
    for (int l = 0; l < 16; ++l) {
        int r = (int)floor(16.0 * pow(pls, (double)l));
        prm.res[l] = r;
        long long r3 = (long long)r * r * r;
        prm.dense[l] = (r3 <= (long long)TSZ) ? 1 : 0;
    }
    size_t smemBytes = (size_t)SMEM_FLOATS * sizeof(float);
    cudaFuncSetAttribute(nerf_kernel, cudaFuncAttributeMaxDynamicSharedMemorySize, (int)smemBytes);
    nerf_kernel<<<NBLOCKS, NTHREADS, smemBytes>>>(
        (const float*)d_in[0], (const float*)d_in[1],
        (const float*)d_in[2], (const float*)d_in[3],
        (const float*)d_in[4], (const float*)d_in[5], (const float*)d_in[6],
        (const float*)d_in[7], (const float*)d_in[8],
        (const float*)d_in[9], (const float*)d_in[10],
        (const float*)d_in[11], (const float*)d_in[12],
        (float*)d_out, prm);
}

// round 5
// speedup vs baseline: 1.5213x; 1.0063x over previous
#include <cuda_runtime.h>
#include <math.h>
#include <stdint.h>

#define NPTS 524288
#define TSZ  524288
#define NTHREADS 256
#define NWARPS_BLK 8
#define NBLOCKS 296
#define FULL 0xffffffffu
#define NPAIR 4   // 8 points per warp iteration

typedef unsigned long long u64;

// ---- shared memory layout (float offsets) ----
#define OFF_WS0PK   0       // [32][32] float2
#define OFF_WS0TPK  2048    // [32][32] float2
#define OFF_WS1PK   4096    // [32][16] float2
#define OFF_WC1PK   5120    // [32][32] float4
#define OFF_WC0PK   9216    // [31][32] float2
#define OFF_WN0PK   11200   // [15][32] float2
#define OFF_WC2     12160   // [64][3]
#define OFF_WN1     12352   // [64][3]
#define OFF_WM0     12544   // [15][32]
#define OFF_WM1     13024   // [32]
#define OFF_BM0     13056   // [32]
#define OFF_BM1     13088   // [1]
#define OFF_DF      13090   // 8 warps * 384 u64
#define SMEM_FLOATS (13090 + NWARPS_BLK * 768)

struct HGParams { int res[16]; int dense[16]; };

__device__ __forceinline__ u64 pk(float lo, float hi) {
    u64 r; asm("mov.b64 %0,{%1,%2};" : "=l"(r) : "f"(lo), "f"(hi)); return r;
}
__device__ __forceinline__ void upk(u64 v, float& lo, float& hi) {
    asm("mov.b64 {%0,%1},%2;" : "=f"(lo), "=f"(hi) : "l"(v));
}
__device__ __forceinline__ u64 bc2(float w) { return pk(w, w); }
__device__ __forceinline__ u64 fma2(u64 a, u64 b, u64 c) {
    u64 d; asm("fma.rn.f32x2 %0,%1,%2,%3;" : "=l"(d) : "l"(a), "l"(b), "l"(c)); return d;
}
__device__ __forceinline__ u64 mul2(u64 a, u64 b) {
    u64 d; asm("mul.rn.f32x2 %0,%1,%2;" : "=l"(d) : "l"(a), "l"(b)); return d;
}
__device__ __forceinline__ u64 add2(u64 a, u64 b) {
    u64 d; asm("add.rn.f32x2 %0,%1,%2;" : "=l"(d) : "l"(a), "l"(b)); return d;
}
__device__ __forceinline__ u64 relu2(u64 v) {
    float a, b; upk(v, a, b); return pk(fmaxf(a, 0.f), fmaxf(b, 0.f));
}
__device__ __forceinline__ u64 allsum2(u64 v) {
    #pragma unroll
    for (int o = 16; o > 0; o >>= 1) v = add2(v, __shfl_xor_sync(FULL, v, o));
    return v;
}
__device__ __forceinline__ float sigm(float v) { return 1.0f / (1.0f + expf(-v)); }
__device__ __forceinline__ float sel3(int lane, float a, float b, float c) {
    return lane == 0 ? a : (lane == 1 ? b : c);
}

extern __shared__ float smem[];

__global__ __launch_bounds__(NTHREADS, 2) void nerf_kernel(
    const float* __restrict__ x,
    const float* __restrict__ tables,
    const float* __restrict__ ws0, const float* __restrict__ ws1,
    const float* __restrict__ wc0, const float* __restrict__ wc1, const float* __restrict__ wc2,
    const float* __restrict__ wn0, const float* __restrict__ wn1,
    const float* __restrict__ wm0, const float* __restrict__ bm0,
    const float* __restrict__ wm1, const float* __restrict__ bm1,
    float* __restrict__ out, HGParams prm)
{
    const int tid = threadIdx.x;
    {
        float2* p = (float2*)(smem + OFF_WS0PK);
        for (int i = tid; i < 1024; i += NTHREADS) { int r = i >> 5, c = i & 31; p[i] = make_float2(ws0[r * 64 + c], ws0[r * 64 + c + 32]); }
        float2* pt_ = (float2*)(smem + OFF_WS0TPK);
        for (int i = tid; i < 1024; i += NTHREADS) { int kk = i >> 5, c = i & 31; pt_[i] = make_float2(ws0[c * 64 + kk], ws0[c * 64 + kk + 32]); }
        float2* p1 = (float2*)(smem + OFF_WS1PK);
        for (int i = tid; i < 512; i += NTHREADS) { int kk = i >> 4, j = i & 15; p1[i] = make_float2(ws1[kk * 16 + j], ws1[(kk + 32) * 16 + j]); }
        float4* pc1 = (float4*)(smem + OFF_WC1PK);
        for (int i = tid; i < 1024; i += NTHREADS) { int kk = i >> 5, c = i & 31;
            pc1[i] = make_float4(wc1[kk * 64 + c], wc1[kk * 64 + c + 32], wc1[(kk + 32) * 64 + c], wc1[(kk + 32) * 64 + c + 32]); }
        float2* pc0 = (float2*)(smem + OFF_WC0PK);
        for (int i = tid; i < 992; i += NTHREADS) { int r = i >> 5, c = i & 31; pc0[i] = make_float2(wc0[r * 64 + c], wc0[r * 64 + c + 32]); }
        float2* pn0 = (float2*)(smem + OFF_WN0PK);
        for (int i = tid; i < 480; i += NTHREADS) { int r = i >> 5, c = i & 31; pn0[i] = make_float2(wn0[r * 64 + c], wn0[r * 64 + c + 32]); }
        for (int i = tid; i < 192; i += NTHREADS) smem[OFF_WC2 + i] = wc2[i];
        for (int i = tid; i < 192; i += NTHREADS) smem[OFF_WN1 + i] = wn1[i];
        for (int i = tid; i < 480; i += NTHREADS) smem[OFF_WM0 + i] = wm0[i];
        for (int i = tid; i < 32;  i += NTHREADS) smem[OFF_WM1 + i] = wm1[i];
        for (int i = tid; i < 32;  i += NTHREADS) smem[OFF_BM0 + i] = bm0[i];
        if (tid == 0) smem[OFF_BM1] = bm1[0];
    }
    __syncthreads();

    const int lane = tid & 31;
    const int warpInBlk = tid >> 5;
    const int gwarp = blockIdx.x * NWARPS_BLK + warpInBlk;
    const int nwarp = gridDim.x * NWARPS_BLK;
    const int j16 = lane & 15;

    const int lvl = lane >> 1;
    const int half = lane & 1;
    const float sxsign = half ? 1.f : -1.f;
    const int res = prm.res[lvl];
    const int dense = prm.dense[lvl];
    const int resm1 = res - 1;
    const float rm1 = (float)resm1;
    const float gscale = rm1 * 0.5f;
    const unsigned my = dense ? (unsigned)res : 2654435761u;
    const unsigned mz = dense ? (unsigned)(res * res) : 805459861u;
    const float2* __restrict__ tabl = ((const float2*)tables) + (size_t)lvl * TSZ;

    const float2* ws0pk  = (const float2*)(smem + OFF_WS0PK);
    const float2* ws0tpk = (const float2*)(smem + OFF_WS0TPK);
    const float2* ws1pk  = (const float2*)(smem + OFF_WS1PK);
    const float4* wc1pk  = (const float4*)(smem + OFF_WC1PK);
    const float2* wc0pk  = (const float2*)(smem + OFF_WC0PK);
    const float2* wn0pk  = (const float2*)(smem + OFF_WN0PK);
    const float* swc2 = smem + OFF_WC2;
    const float* swn1 = smem + OFF_WN1;
    const float* swm0 = smem + OFF_WM0;
    const float* swm1 = smem + OFF_WM1;
    const float* sbm0 = smem + OFF_BM0;
    u64* dfw = ((u64*)(smem + OFF_DF)) + warpInBlk * 384;

    for (int pbase = gwarp * (2 * NPAIR); pbase < NPTS; pbase += nwarp * (2 * NPAIR)) {
        // ================= hashgrid gather =================
        u64 encP[NPAIR];
        #pragma unroll
        for (int P = 0; P < NPAIR; ++P) {
            float e2[2], gx2[2], gy2[2], gz2[2];
            #pragma unroll
            for (int q = 0; q < 2; ++q) {
                const float* xp = x + (size_t)(pbase + 2 * P + q) * 6;
                float X = fminf(fmaxf((__ldg(xp + 0) + 1.0f) * 0.5f, 0.0f), 1.0f);
                float Y = fminf(fmaxf((__ldg(xp + 1) + 1.0f) * 0.5f, 0.0f), 1.0f);
                float Z = fminf(fmaxf((__ldg(xp + 2) + 1.0f) * 0.5f, 0.0f), 1.0f);
                float px = X * rm1, py = Y * rm1, pz = Z * rm1;
                float fpx = floorf(px), fpy = floorf(py), fpz = floorf(pz);
                float fx = px - fpx, fy = py - fpy, fz = pz - fpz;
                int ix = (int)fpx, iy = (int)fpy, iz = (int)fpz;
                int ix1 = min(ix + 1, resm1), iy1 = min(iy + 1, resm1), iz1 = min(iz + 1, resm1);
                unsigned tx = half ? (unsigned)ix1 : (unsigned)ix;
                unsigned ay[2] = { (unsigned)iy * my, (unsigned)iy1 * my };
                unsigned az[2] = { (unsigned)iz * mz, (unsigned)iz1 * mz };
                float2 tv[4];
                #pragma unroll
                for (int j = 0; j < 4; ++j) {
                    int by = j >> 1, bz = j & 1;
                    unsigned idx = dense ? (tx + ay[by] + az[bz])
                                         : ((tx ^ ay[by] ^ az[bz]) & (unsigned)(TSZ - 1));
                    tv[j] = __ldg(tabl + idx);
                }
                float oy = 1.f - fy, oz = 1.f - fz;
                float S0 = 0.f, S1 = 0.f, Sy0 = 0.f, Sy1 = 0.f, Sz0 = 0.f, Sz1 = 0.f;
                #pragma unroll
                for (int j = 0; j < 4; ++j) {
                    int by = j >> 1, bz = j & 1;
                    float wy = by ? fy : oy, wz = bz ? fz : oz;
                    float wyz = wy * wz;
                    S0 = fmaf(tv[j].x, wyz, S0);  S1 = fmaf(tv[j].y, wyz, S1);
                    float syw = by ? wz : -wz;
                    Sy0 = fmaf(tv[j].x, syw, Sy0); Sy1 = fmaf(tv[j].y, syw, Sy1);
                    float szw = bz ? wy : -wy;
                    Sz0 = fmaf(tv[j].x, szw, Sz0); Sz1 = fmaf(tv[j].y, szw, Sz1);
                }
                float wxc = half ? fx : 1.f - fx;
                float So  = half ? S1 : S0,  Sp  = half ? S0 : S1;
                float Syo = half ? Sy1 : Sy0, Syp = half ? Sy0 : Sy1;
                float Szo = half ? Sz1 : Sz0, Szp = half ? Sz0 : Sz1;
                u64 A = __shfl_xor_sync(FULL, pk(wxc * Sp, sxsign * Sp), 1);
                u64 B = __shfl_xor_sync(FULL, pk(wxc * Syp, wxc * Szp), 1);
                float er, gxr, gyr, gzr;
                upk(A, er, gxr); upk(B, gyr, gzr);
                e2[q]  = fmaf(wxc, So, er);
                gx2[q] = (fmaf(sxsign, So, gxr)) * gscale;
                gy2[q] = (fmaf(wxc, Syo, gyr)) * gscale;
                gz2[q] = (fmaf(wxc, Szo, gzr)) * gscale;
            }
            encP[P] = pk(e2[0], e2[1]);
            dfw[(P * 3 + 0) * 32 + lane] = pk(gx2[0], gx2[1]);
            dfw[(P * 3 + 1) * 32 + lane] = pk(gy2[0], gy2[1]);
            dfw[(P * 3 + 2) * 32 + lane] = pk(gz2[0], gz2[1]);
        }

        // ================= density layer0 =================
        u64 h1[NPAIR][2];
        #pragma unroll
        for (int P = 0; P < NPAIR; ++P) { h1[P][0] = 0ull; h1[P][1] = 0ull; }
        #pragma unroll 4
        for (int i = 0; i < 32; ++i) {
            float2 w = ws0pk[i * 32 + lane];
            u64 w0 = bc2(w.x), w1 = bc2(w.y);
            #pragma unroll
            for (int P = 0; P < NPAIR; ++P) {
                u64 e = __shfl_sync(FULL, encP[P], i);
                h1[P][0] = fma2(e, w0, h1[P][0]);
                h1[P][1] = fma2(e, w1, h1[P][1]);
            }
        }
        #pragma unroll
        for (int P = 0; P < NPAIR; ++P) { h1[P][0] = relu2(h1[P][0]); h1[P][1] = relu2(h1[P][1]); }

        // ======== fused layer1 + backward ========
        u64 geo[NPAIR], genc[NPAIR];
        #pragma unroll
        for (int P = 0; P < NPAIR; ++P) { geo[P] = 0ull; genc[P] = 0ull; }
        #pragma unroll 2
        for (int kk = 0; kk < 32; ++kk) {
            float2 wab = ws1pk[kk * 16 + j16];
            float2 m01 = ws1pk[kk * 16];
            float2 wst = ws0tpk[kk * 32 + lane];
            u64 wA = bc2(wab.x), wB = bc2(wab.y);
            u64 wsA = bc2(wst.x), wsB = bc2(wst.y);
            #pragma unroll
            for (int P = 0; P < NPAIR; ++P) {
                u64 a = __shfl_sync(FULL, h1[P][0], kk);
                u64 b = __shfl_sync(FULL, h1[P][1], kk);
                geo[P] = fma2(a, wA, fma2(b, wB, geo[P]));
                float alo, ahi, blo, bhi; upk(a, alo, ahi); upk(b, blo, bhi);
                u64 da = pk(alo > 0.f ? m01.x : 0.f, ahi > 0.f ? m01.x : 0.f);
                u64 db = pk(blo > 0.f ? m01.y : 0.f, bhi > 0.f ? m01.y : 0.f);
                genc[P] = fma2(da, wsA, fma2(db, wsB, genc[P]));
            }
        }

        // ================= normal =================
        #pragma unroll
        for (int P = 0; P < NPAIR; ++P) {
            u64 sx = allsum2(mul2(genc[P], dfw[(P * 3 + 0) * 32 + lane]));
            u64 sy = allsum2(mul2(genc[P], dfw[(P * 3 + 1) * 32 + lane]));
            u64 sz = allsum2(mul2(genc[P], dfw[(P * 3 + 2) * 32 + lane]));
            float nx0, nx1, ny0, ny1, nz0, nz1;
            upk(sx, nx0, nx1); upk(sy, ny0, ny1); upk(sz, nz0, nz1);
            #pragma unroll
            for (int q = 0; q < 2; ++q) {
                float n0 = -(q ? nx1 : nx0), n1 = -(q ? ny1 : ny0), n2 = -(q ? nz1 : nz0);
                float inv = 1.0f / fmaxf(sqrtf(n0 * n0 + n1 * n1 + n2 * n2), 1e-8f);
                if (lane < 3)
                    out[(size_t)NPTS * 16 + (size_t)(pbase + P * 2 + q) * 3 + lane] =
                        sel3(lane, n0 * inv, n1 * inv, n2 * inv);
            }
        }

        // ================= pred_normal =================
        {
            u64 t0[NPAIR], t1[NPAIR];
            #pragma unroll
            for (int P = 0; P < NPAIR; ++P) { t0[P] = 0ull; t1[P] = 0ull; }
            #pragma unroll
            for (int i = 0; i < 15; ++i) {
                float2 w = wn0pk[i * 32 + lane];
                u64 w0 = bc2(w.x), w1 = bc2(w.y);
                #pragma unroll
                for (int P = 0; P < NPAIR; ++P) {
                    u64 g = __shfl_sync(FULL, geo[P], i + 1);
                    t0[P] = fma2(g, w0, t0[P]);
                    t1[P] = fma2(g, w1, t1[P]);
                }
            }
            #pragma unroll
            for (int P = 0; P < NPAIR; ++P) { t0[P] = relu2(t0[P]); t1[P] = relu2(t1[P]); }
            #pragma unroll
            for (int P = 0; P < NPAIR; ++P) {
                float pn[3][2];
                #pragma unroll
                for (int d = 0; d < 3; ++d) {
                    u64 wA = bc2(swn1[lane * 3 + d]);
                    u64 wB = bc2(swn1[(lane + 32) * 3 + d]);
                    u64 s = allsum2(fma2(t0[P], wA, mul2(t1[P], wB)));
                    upk(s, pn[d][0], pn[d][1]);
                }
                #pragma unroll
                for (int q = 0; q < 2; ++q) {
                    float n0 = pn[0][q], n1 = pn[1][q], n2 = pn[2][q];
                    float inv = 1.0f / fmaxf(sqrtf(n0 * n0 + n1 * n1 + n2 * n2), 1e-8f);
                    if (lane < 3)
                        out[(size_t)NPTS * 19 + (size_t)(pbase + P * 2 + q) * 3 + lane] =
                            sel3(lane, n0 * inv, n1 * inv, n2 * inv);
                }
            }
        }

        // ================= color =================
        {
            u64 ca[NPAIR], cb[NPAIR];
            #pragma unroll
            for (int P = 0; P < NPAIR; ++P) { ca[P] = 0ull; cb[P] = 0ull; }
            #pragma unroll
            for (int i = 0; i < 15; ++i) {
                float2 w = wc0pk[(16 + i) * 32 + lane];
                u64 w0 = bc2(w.x), w1 = bc2(w.y);
                #pragma unroll
                for (int P = 0; P < NPAIR; ++P) {
                    u64 g = __shfl_sync(FULL, geo[P], i + 1);
                    ca[P] = fma2(g, w0, ca[P]);
                    cb[P] = fma2(g, w1, cb[P]);
                }
            }
            // SH part: compute each basis inline, accumulate immediately (no shp array)
            #pragma unroll
            for (int P = 0; P < NPAIR; ++P) {
                const float* xp0 = x + (size_t)(pbase + 2 * P) * 6;
                const float* xp1 = x + (size_t)(pbase + 2 * P + 1) * 6;
                u64 X = pk(__ldg(xp0 + 3), __ldg(xp1 + 3));
                u64 Y = pk(__ldg(xp0 + 4), __ldg(xp1 + 4));
                u64 Z = pk(__ldg(xp0 + 5), __ldg(xp1 + 5));
                u64 XY = mul2(X, Y), XZ = mul2(X, Z), YZ = mul2(Y, Z);
                u64 X2 = mul2(X, X), Y2 = mul2(Y, Y), Z2 = mul2(Z, Z);
                u64 a = ca[P], b = cb[P];
                {
                    #define ACC(ii, expr) { u64 sh_ = (expr); float2 w_ = wc0pk[(ii) * 32 + lane]; \
                        a = fma2(sh_, bc2(w_.x), a); b = fma2(sh_, bc2(w_.y), b); }
                    ACC(0, bc2(0.28209479177387814f));
                    ACC(1, mul2(bc2(-0.48860251190291987f), Y));
                    ACC(2, mul2(bc2(0.48860251190291987f), Z));
                    ACC(3, mul2(bc2(-0.48860251190291987f), X));
                    ACC(4, mul2(bc2(1.0925484305920792f), XY));
                    ACC(5, mul2(bc2(-1.0925484305920792f), YZ));
                    ACC(6, fma2(bc2(0.94617469575756f), Z2, bc2(-0.31539156525252005f)));
                    ACC(7, mul2(bc2(-1.0925484305920792f), XZ));
                    ACC(8, mul2(bc2(0.5462742152960396f), fma2(Y2, bc2(-1.f), X2)));
                    ACC(9, mul2(bc2(0.5900435899266435f), mul2(Y, fma2(bc2(-3.f), X2, Y2))));
                    ACC(10, mul2(bc2(2.890611442640554f), mul2(XY, Z)));
                    ACC(11, mul2(bc2(0.4570457994644657f), mul2(Y, fma2(bc2(-5.f), Z2, bc2(1.f)))));
                    ACC(12, mul2(bc2(0.3731763325901154f), mul2(Z, fma2(bc2(5.f), Z2, bc2(-3.f)))));
                    ACC(13, mul2(bc2(0.4570457994644657f), mul2(X, fma2(bc2(-5.f), Z2, bc2(1.f)))));
                    ACC(14, mul2(bc2(1.445305721320277f), mul2(Z, fma2(Y2, bc2(-1.f), X2))));
                    ACC(15, mul2(bc2(0.5900435899266435f), mul2(X, fma2(bc2(-3.f), Y2, X2))));
                    #undef ACC
                }
                ca[P] = relu2(a); cb[P] = relu2(b);
            }
            u64 c10[NPAIR], c11[NPAIR];
            #pragma unroll
            for (int P = 0; P < NPAIR; ++P) { c10[P] = 0ull; c11[P] = 0ull; }
            #pragma unroll 2
            for (int kk = 0; kk < 32; ++kk) {
                float4 w4 = wc1pk[kk * 32 + lane];
                u64 w00 = bc2(w4.x), w01 = bc2(w4.y), w10 = bc2(w4.z), w11 = bc2(w4.w);
                #pragma unroll
                for (int P = 0; P < NPAIR; ++P) {
                    u64 hA = __shfl_sync(FULL, ca[P], kk);
                    u64 hB = __shfl_sync(FULL, cb[P], kk);
                    c10[P] = fma2(hA, w00, fma2(hB, w10, c10[P]));
                    c11[P] = fma2(hA, w01, fma2(hB, w11, c11[P]));
                }
            }
            #pragma unroll
            for (int P = 0; P < NPAIR; ++P) { c10[P] = relu2(c10[P]); c11[P] = relu2(c11[P]); }
            #pragma unroll
            for (int d = 0; d < 3; ++d) {
                u64 wA = bc2(swc2[lane * 3 + d]);
                u64 wB = bc2(swc2[(lane + 32) * 3 + d]);
                #pragma unroll
                for (int P = 0; P < NPAIR; ++P) {
                    u64 s = allsum2(fma2(c10[P], wA, mul2(c11[P], wB)));
                    float r0, r1; upk(s, r0, r1);
                    if (lane == d) {
                        out[(size_t)NPTS * 22 + (size_t)(pbase + P * 2 + 0) * 3 + d] = sigm(r0);
                        out[(size_t)NPTS * 22 + (size_t)(pbase + P * 2 + 1) * 3 + d] = sigm(r1);
                    }
                }
            }
        }

        // ================= mirror head =================
        {
            u64 m[NPAIR];
            #pragma unroll
            for (int P = 0; P < NPAIR; ++P) m[P] = bc2(sbm0[lane]);
            #pragma unroll
            for (int i = 0; i < 15; ++i) {
                u64 w = bc2(swm0[i * 32 + lane]);
                #pragma unroll
                for (int P = 0; P < NPAIR; ++P) {
                    u64 g = __shfl_sync(FULL, geo[P], i + 1);
                    m[P] = fma2(g, w, m[P]);
                }
            }
            float bm1v = smem[OFF_BM1];
            u64 wv = bc2(swm1[lane]);
            #pragma unroll
            for (int P = 0; P < NPAIR; ++P) {
                float a, b; upk(m[P], a, b);
                a = a > 0.f ? a : 0.01f * a;
                b = b > 0.f ? b : 0.01f * b;
                u64 s = allsum2(mul2(pk(a, b), wv));
                float s0, s1; upk(s, s0, s1);
                if (lane == 0) {
                    out[(size_t)NPTS * 25 + (pbase + P * 2 + 0)] = sigm(s0 + bm1v);
                    out[(size_t)NPTS * 25 + (pbase + P * 2 + 1)] = sigm(s1 + bm1v);
                }
            }
        }

        // ================= sigma + geo_feat =================
        #pragma unroll
        for (int P = 0; P < NPAIR; ++P) {
            float gA, gB; upk(geo[P], gA, gB);
            size_t p0 = (size_t)(pbase + P * 2), p1 = p0 + 1;
            if (lane == 0) { out[p0] = gA; out[p1] = gB; }
            if (lane >= 1 && lane < 16) {
                out[(size_t)NPTS + p0 * 15 + (lane - 1)] = gA;
                out[(size_t)NPTS + p1 * 15 + (lane - 1)] = gB;
            }
        }
    }
}

extern "C" void kernel_launch(void* const* d_in, const int* in_sizes, int n_in,
                              void* d_out, int out_size) {
    (void)in_sizes; (void)n_in; (void)out_size;
    HGParams prm;
    double pls = exp2(log2(2048.0 * 1.0 / 16.0) / 15.0);
    for (int l = 0; l < 16; ++l) {
        int r = (int)floor(16.0 * pow(pls, (double)l));
        prm.res[l] = r;
        long long r3 = (long long)r * r * r;
        prm.dense[l] = (r3 <= (long long)TSZ) ? 1 : 0;
    }
    size_t smemBytes = (size_t)SMEM_FLOATS * sizeof(float);
    cudaFuncSetAttribute(nerf_kernel, cudaFuncAttributeMaxDynamicSharedMemorySize, (int)smemBytes);
    nerf_kernel<<<NBLOCKS, NTHREADS, smemBytes>>>(
        (const float*)d_in[0], (const float*)d_in[1],
        (const float*)d_in[2], (const float*)d_in[3],
        (const float*)d_in[4], (const float*)d_in[5], (const float*)d_in[6],
        (const float*)d_in[7], (const float*)d_in[8],
        (const float*)d_in[9], (const float*)d_in[10],
        (const float*)d_in[11], (const float*)d_in[12],
        (float*)d_out, prm);
}